// round 5
// baseline (speedup 1.0000x reference)
#include <cuda_runtime.h>
#include <math.h>

#define N0 50000
#define E0 1600000
#define K1 40000
#define K2 32000
#define NB_SCAN 49   // ceil(N0/1024)

// ---------------- scratch (device globals; no runtime allocation) ----------------
__device__ float g_x1[N0*128];
__device__ float g_agg[N0*128];
__device__ float g_t[K1*64];
__device__ float g_x2[K1*64];
__device__ float g_x3[K2*64];
__device__ float g_u1[K1*64];
__device__ float g_x4[K1*128];
__device__ float g_u2[N0*128];
__device__ float g_x5[N0*128];
__device__ int   g_rowptr[N0+1];
__device__ int   g_fill[N0];
__device__ int   g_part[64];
__device__ int   g_partx[66];
__device__ int   g_esrc[E0];
__device__ float g_score[N0];
__device__ unsigned g_key[N0];
__device__ int   g_map1[N0];
__device__ int   g_perm1[K1];
__device__ int   g_map2[K1];
__device__ int   g_perm2[K2];
__device__ int   g_map02[N0];
__device__ int   g_perm02[K2];
__device__ float g_wT[10*128*128];
__device__ float g_norm;
__device__ unsigned g_hist[256];
__device__ unsigned g_prefix;
__device__ int   g_remaining;

// ---------------- CSR build ----------------
__global__ void edge_count_kernel(const int* __restrict__ dst)
{
    int e = blockIdx.x*blockDim.x + threadIdx.x;
    if (e < E0) atomicAdd(&g_fill[dst[e]], 1);
}

__device__ __forceinline__ int block_scan_incl(int val, int& total, int* ws)
{
    int lane = threadIdx.x & 31, wid = threadIdx.x >> 5;
    int x = val;
    #pragma unroll
    for (int off = 1; off < 32; off <<= 1){
        int y = __shfl_up_sync(0xffffffffu, x, off);
        if (lane >= off) x += y;
    }
    if (lane == 31) ws[wid] = x;
    __syncthreads();
    if (wid == 0){
        int s = ws[lane];
        #pragma unroll
        for (int off = 1; off < 32; off <<= 1){
            int y = __shfl_up_sync(0xffffffffu, s, off);
            if (lane >= off) s += y;
        }
        ws[lane] = s;
    }
    __syncthreads();
    int res = x + (wid ? ws[wid-1] : 0);
    total = ws[31];
    __syncthreads();
    return res;
}

// generic single-block exclusive scan (blockDim = 1024)
__global__ void scan_kernel(const int* __restrict__ in, int* __restrict__ out, int n)
{
    __shared__ int ws[32];
    int run = 0;
    for (int base = 0; base < n; base += 1024){
        int i = base + threadIdx.x;
        int v = (i < n) ? in[i] : 0;
        int tot; int incl = block_scan_incl(v, tot, ws);
        if (i < n) out[i] = run + incl - v;
        run += tot;
    }
    if (threadIdx.x == 0) out[n] = run;
}

// per-block reduce of degrees
__global__ void deg_reduce_kernel(const int* __restrict__ in, int* __restrict__ part, int n)
{
    __shared__ int ws[32];
    int i = blockIdx.x*1024 + threadIdx.x;
    int v = (i < n) ? in[i] : 0;
    int lane = threadIdx.x & 31, wid = threadIdx.x >> 5;
    #pragma unroll
    for (int off = 16; off; off >>= 1) v += __shfl_down_sync(0xffffffffu, v, off);
    if (lane == 0) ws[wid] = v;
    __syncthreads();
    if (wid == 0){
        v = ws[lane];
        #pragma unroll
        for (int off = 16; off; off >>= 1) v += __shfl_down_sync(0xffffffffu, v, off);
        if (lane == 0) part[blockIdx.x] = v;
    }
}

// per-block scan + offset -> rowptr
__global__ void deg_apply_kernel(const int* __restrict__ in, const int* __restrict__ partx,
                                 int* __restrict__ rowptr, int n)
{
    __shared__ int ws[32];
    int i = blockIdx.x*1024 + threadIdx.x;
    int v = (i < n) ? in[i] : 0;
    int tot; int incl = block_scan_incl(v, tot, ws);
    if (i < n) rowptr[i] = partx[blockIdx.x] + incl - v;
    if (i == n) rowptr[n] = partx[gridDim.x];
}

// countdown scatter: consumes g_fill (degrees) so no re-zero needed
__global__ void edge_scatter_kernel(const int* __restrict__ src, const int* __restrict__ dst)
{
    int e = blockIdx.x*blockDim.x + threadIdx.x;
    if (e < E0){
        int d = dst[e];
        int off = atomicSub(&g_fill[d], 1) - 1;
        g_esrc[g_rowptr[d] + off] = src[e];
    }
}

// ---------------- fused transpose of all 10 weight matrices ----------------
__global__ void transpose_all_kernel(
    const float* w0, const float* w1, const float* w2, const float* w3, const float* w4,
    const float* w5, const float* w6, const float* w7, const float* w8, const float* w9,
    float* __restrict__ wT)
{
    const float* ws[10] = {w0,w1,w2,w3,w4,w5,w6,w7,w8,w9};
    const int CO[10] = {128,128,64,64,64,64,128,128,128,128};
    const int CI[10] = {128,128,128,128,64,64,64,64,128,128};
    int m = blockIdx.y;
    int idx = blockIdx.x*blockDim.x + threadIdx.x;
    int nEl = CO[m]*CI[m];
    if (idx < nEl){
        int r = idx / CI[m], c = idx % CI[m];
        wT[m*16384 + c*CO[m] + r] = ws[m][idx];
    }
}

// ---------------- aggregation: warp per node, vectorized row gather ----------------
template<int C>
__global__ void agg_kernel(const float* __restrict__ xin, float* __restrict__ out,
                           const int* __restrict__ perm, const int* __restrict__ mapping, int n)
{
    int warp = (blockIdx.x*blockDim.x + threadIdx.x) >> 5;
    int lane = threadIdx.x & 31;
    if (warp >= n) return;
    int old = perm ? perm[warp] : warp;
    int beg = g_rowptr[old], end = g_rowptr[old+1];
    if constexpr (C == 128){
        float4 acc = make_float4(0.f,0.f,0.f,0.f);
        for (int b = beg; b < end; b += 32){
            int e = b + lane;
            int s = -1;
            if (e < end){ s = g_esrc[e]; if (mapping) s = mapping[s]; }
            int cnt = min(32, end - b);
            for (int j = 0; j < cnt; j++){
                int sj = __shfl_sync(0xffffffffu, s, j);
                if (sj >= 0){
                    float4 v = ((const float4*)(xin + (size_t)sj*128))[lane];
                    acc.x += v.x; acc.y += v.y; acc.z += v.z; acc.w += v.w;
                }
            }
        }
        ((float4*)(out + (size_t)warp*128))[lane] = acc;
    } else {
        float2 acc = make_float2(0.f,0.f);
        for (int b = beg; b < end; b += 32){
            int e = b + lane;
            int s = -1;
            if (e < end){ s = g_esrc[e]; if (mapping) s = mapping[s]; }
            int cnt = min(32, end - b);
            for (int j = 0; j < cnt; j++){
                int sj = __shfl_sync(0xffffffffu, s, j);
                if (sj >= 0){
                    float2 v = ((const float2*)(xin + (size_t)sj*64))[lane];
                    acc.x += v.x; acc.y += v.y;
                }
            }
        }
        ((float2*)(out + (size_t)warp*64))[lane] = acc;
    }
}

// ---------------- tf32 split helpers ----------------
__device__ __forceinline__ void tf32_split(float a, float& hi, float& lo)
{
    unsigned h;
    asm("cvt.rna.tf32.f32 %0, %1;" : "=r"(h) : "f"(a));
    float hf = __uint_as_float(h);
    float l = a - hf;              // exact in fp32
    unsigned lu;
    asm("cvt.rna.tf32.f32 %0, %1;" : "=r"(lu) : "f"(l));
    hi = hf; lo = __uint_as_float(lu);
}

#define MMA_TF32(d, a0,a1,a2,a3, b0,b1) \
    asm volatile("mma.sync.aligned.m16n8k8.row.col.f32.tf32.tf32.f32 " \
        "{%0,%1,%2,%3}, {%4,%5,%6,%7}, {%8,%9}, {%0,%1,%2,%3};" \
        : "+f"((d)[0]), "+f"((d)[1]), "+f"((d)[2]), "+f"((d)[3]) \
        : "r"(a0), "r"(a1), "r"(a2), "r"(a3), "r"(b0), "r"(b1))

// ---------------- tensor-core GEMM: out = [relu](D + A1*W1t [+ A2*W2t] [+ b]) ----------------
// 3-term tf32 split (hi*hi + hi*lo + lo*hi), error ~2^-22: preserves TopK selection.
// PTX m16n8k8 tf32 A fragment: a0=A[g][t], a1=A[g+8][t], a2=A[g][t+4], a3=A[g+8][t+4]
// (row alternates first!)  B: b0=B[t][g], b1=B[t+4][g].  C: c0,c1 row g cols 2t,2t+1; c2,c3 row g+8.
template<int BN, int CIN, bool DUAL, bool RELU, bool GATHER>
__global__ void __launch_bounds__(256) gemm_tc_kernel(
    const float* __restrict__ A1, const float* __restrict__ A2,
    const float* __restrict__ W1, const float* __restrict__ W2,   // transposed [CIN][BN]
    const float* __restrict__ bias, const float* __restrict__ D,
    float* __restrict__ out, int n,
    const int* __restrict__ perm, const float* __restrict__ score)
{
    constexpr int BM = 128, BK = 16, TPB = 256;
    constexpr int BMp = 136, BNp = BN + 8;
    constexpr int AV = (BM*BK/4)/TPB;
    constexpr int BV = (BK*BN/4)/TPB;
    constexpr int TILES = CIN/BK;
    constexpr int T = (DUAL?2:1)*TILES;
    constexpr int MT = 2;
    constexpr int NT = BN/16;

    __shared__ float As[2][BK][BMp];
    __shared__ float Bs[2][BK][BNp];

    int tid = threadIdx.x, lane = tid & 31, warp = tid >> 5;
    int m0 = (warp >> 1) * 32;
    int n0 = (warp & 1) * (BN/2);
    int row0 = blockIdx.x * BM;
    int gid = lane >> 2, tig = lane & 3;

    int am[AV], akq[AV], aar[AV]; float asc[AV];
    #pragma unroll
    for (int u = 0; u < AV; u++){
        int f = tid + u*TPB;
        am[u] = f >> 2; akq[u] = (f & 3) << 2;
        int r = row0 + am[u];
        aar[u] = -1; asc[u] = 1.f;
        if (r < n){
            int ar = r;
            if (GATHER){ ar = perm[r]; asc[u] = score[ar]; }
            aar[u] = ar;
        }
    }
    int bkk[BV], bc4[BV];
    #pragma unroll
    for (int u = 0; u < BV; u++){
        int f = tid + u*TPB;
        bkk[u] = f / (BN/4); bc4[u] = (f % (BN/4)) << 2;
    }

    float4 ra[AV], rb[BV];
    auto load_tile = [&](int t){
        int ph = DUAL ? (t / TILES) : 0;
        int k0 = (t % TILES) * BK;
        const float* A = (DUAL && ph) ? A2 : A1;
        const float* W = (DUAL && ph) ? W2 : W1;
        #pragma unroll
        for (int u = 0; u < AV; u++){
            float4 v = make_float4(0.f,0.f,0.f,0.f);
            if (aar[u] >= 0){
                v = *(const float4*)(A + (size_t)aar[u]*CIN + k0 + akq[u]);
                if (GATHER){ v.x*=asc[u]; v.y*=asc[u]; v.z*=asc[u]; v.w*=asc[u]; }
            }
            ra[u] = v;
        }
        #pragma unroll
        for (int u = 0; u < BV; u++)
            rb[u] = *(const float4*)(W + (size_t)(k0 + bkk[u])*BN + bc4[u]);
    };
    auto store_split = [&](){
        #pragma unroll
        for (int u = 0; u < AV; u++){
            const float* s = (const float*)&ra[u];
            #pragma unroll
            for (int q = 0; q < 4; q++){
                float hi, lo; tf32_split(s[q], hi, lo);
                As[0][akq[u]+q][am[u]] = hi;
                As[1][akq[u]+q][am[u]] = lo;
            }
        }
        #pragma unroll
        for (int u = 0; u < BV; u++){
            const float* s = (const float*)&rb[u];
            #pragma unroll
            for (int q = 0; q < 4; q++){
                float hi, lo; tf32_split(s[q], hi, lo);
                Bs[0][bkk[u]][bc4[u]+q] = hi;
                Bs[1][bkk[u]][bc4[u]+q] = lo;
            }
        }
    };

    float acc[MT][NT][4];
    #pragma unroll
    for (int mi = 0; mi < MT; mi++)
        #pragma unroll
        for (int ni = 0; ni < NT; ni++)
            #pragma unroll
            for (int q = 0; q < 4; q++) acc[mi][ni][q] = 0.f;

    load_tile(0);
    for (int t = 0; t < T; t++){
        store_split();
        __syncthreads();
        if (t + 1 < T) load_tile(t + 1);
        #pragma unroll
        for (int kk = 0; kk < 2; kk++){
            int ko = kk * 8;
            unsigned ah[MT][4], al[MT][4];
            #pragma unroll
            for (int mi = 0; mi < MT; mi++){
                int mb = m0 + mi*16 + gid;
                // CORRECT PTX layout: a0=(r,k) a1=(r+8,k) a2=(r,k+4) a3=(r+8,k+4)
                ah[mi][0] = __float_as_uint(As[0][ko+tig  ][mb  ]);
                ah[mi][1] = __float_as_uint(As[0][ko+tig  ][mb+8]);
                ah[mi][2] = __float_as_uint(As[0][ko+tig+4][mb  ]);
                ah[mi][3] = __float_as_uint(As[0][ko+tig+4][mb+8]);
                al[mi][0] = __float_as_uint(As[1][ko+tig  ][mb  ]);
                al[mi][1] = __float_as_uint(As[1][ko+tig  ][mb+8]);
                al[mi][2] = __float_as_uint(As[1][ko+tig+4][mb  ]);
                al[mi][3] = __float_as_uint(As[1][ko+tig+4][mb+8]);
            }
            #pragma unroll
            for (int ni = 0; ni < NT; ni++){
                int nb = n0 + ni*8 + gid;
                unsigned bh0 = __float_as_uint(Bs[0][ko+tig  ][nb]);
                unsigned bh1 = __float_as_uint(Bs[0][ko+tig+4][nb]);
                unsigned bl0 = __float_as_uint(Bs[1][ko+tig  ][nb]);
                unsigned bl1 = __float_as_uint(Bs[1][ko+tig+4][nb]);
                #pragma unroll
                for (int mi = 0; mi < MT; mi++){
                    MMA_TF32(acc[mi][ni], ah[mi][0],ah[mi][1],ah[mi][2],ah[mi][3], bh0,bh1);
                    MMA_TF32(acc[mi][ni], ah[mi][0],ah[mi][1],ah[mi][2],ah[mi][3], bl0,bl1);
                    MMA_TF32(acc[mi][ni], al[mi][0],al[mi][1],al[mi][2],al[mi][3], bh0,bh1);
                }
            }
        }
        __syncthreads();
    }

    #pragma unroll
    for (int mi = 0; mi < MT; mi++){
        #pragma unroll
        for (int ni = 0; ni < NT; ni++){
            int cc = n0 + ni*8 + tig*2;
            #pragma unroll
            for (int h = 0; h < 2; h++){
                int rr = row0 + m0 + mi*16 + gid + h*8;
                if (rr < n){
                    float v0 = acc[mi][ni][h*2+0];
                    float v1 = acc[mi][ni][h*2+1];
                    if (bias){ v0 += __ldg(&bias[cc]); v1 += __ldg(&bias[cc+1]); }
                    if (D){ v0 += D[(size_t)rr*BN + cc]; v1 += D[(size_t)rr*BN + cc + 1]; }
                    if (RELU){ v0 = fmaxf(v0, 0.f); v1 = fmaxf(v1, 0.f); }
                    *(float2*)(out + (size_t)rr*BN + cc) = make_float2(v0, v1);
                }
            }
        }
    }
}

// ---------------- topk pooling ----------------
template<int C>
__global__ void norm_kernel(const float* __restrict__ w)
{
    int lane = threadIdx.x;
    float p = 0.f;
    #pragma unroll
    for (int i = 0; i < C/32; i++){ float v = w[i*32 + lane]; p += v*v; }
    #pragma unroll
    for (int off = 16; off; off >>= 1) p += __shfl_xor_sync(0xffffffffu, p, off);
    if (lane == 0) g_norm = sqrtf(p);
}

template<int C>
__global__ void score_kernel(const float* __restrict__ x, const float* __restrict__ w, int n)
{
    int gw = blockIdx.x*(blockDim.x>>5) + (threadIdx.x>>5);
    int lane = threadIdx.x & 31;
    if (gw >= n) return;
    float p;
    if constexpr (C == 128){
        float4 xv = ((const float4*)(x + (size_t)gw*128))[lane];
        float4 wv = ((const float4*)w)[lane];
        p = xv.x*wv.x + xv.y*wv.y + xv.z*wv.z + xv.w*wv.w;
    } else {
        float2 xv = ((const float2*)(x + (size_t)gw*64))[lane];
        float2 wv = ((const float2*)w)[lane];
        p = xv.x*wv.x + xv.y*wv.y;
    }
    #pragma unroll
    for (int off = 16; off; off >>= 1) p += __shfl_xor_sync(0xffffffffu, p, off);
    if (lane == 0){
        float s = tanhf(p / g_norm);
        g_score[gw] = s;
        unsigned u = __float_as_uint(s);
        u = (u & 0x80000000u) ? ~u : (u | 0x80000000u);
        g_key[gw] = u;
    }
}

__global__ void sel_init_kernel(int k)
{
    int t = threadIdx.x;
    if (t < 256) g_hist[t] = 0;
    if (t == 0){ g_prefix = 0; g_remaining = k; }
}

__global__ void sel_hist_kernel(int n, int pass)
{
    __shared__ unsigned sh[256];
    for (int t = threadIdx.x; t < 256; t += blockDim.x) sh[t] = 0;
    __syncthreads();
    int i = blockIdx.x*blockDim.x + threadIdx.x;
    if (i < n){
        unsigned key = g_key[i];
        bool ok;
        if (pass == 3) ok = true;
        else { int shf = (pass+1)*8; ok = ((key >> shf) == (g_prefix >> shf)); }
        if (ok) atomicAdd(&sh[(key >> (pass*8)) & 255], 1u);
    }
    __syncthreads();
    for (int t = threadIdx.x; t < 256; t += blockDim.x){
        unsigned v = sh[t]; if (v) atomicAdd(&g_hist[t], v);
    }
}

__global__ void sel_scan_kernel(int pass)
{
    if (threadIdx.x == 0){
        unsigned r = (unsigned)g_remaining;
        unsigned c = 0; int b = 255;
        for (; b > 0; b--){
            unsigned h = g_hist[b];
            if (c + h >= r) break;
            c += h;
        }
        g_prefix |= ((unsigned)b) << (pass*8);
        g_remaining = (int)(r - c);
    }
    __syncthreads();
    for (int t = threadIdx.x; t < 256; t += blockDim.x) g_hist[t] = 0;
}

// single block (1024 threads): count strictly-greater, then mark/compact top-k
__global__ void compact_kernel(int* __restrict__ mapping, int* __restrict__ perm, int n, int k)
{
    __shared__ int ws[32];
    unsigned thr = g_prefix;
    int local = 0;
    for (int base = 0; base < n; base += 1024){
        int i = base + threadIdx.x;
        if (i < n) local += (g_key[i] > thr) ? 1 : 0;
    }
    int totG; block_scan_incl(local, totG, ws);
    int need_eq = k - totG;
    int run_eq = 0, run_sel = 0;
    for (int base = 0; base < n; base += 1024){
        int i = base + threadIdx.x;
        int gt = 0, eq = 0;
        if (i < n){
            unsigned kv = g_key[i];
            gt = (kv > thr); eq = (kv == thr);
        }
        int tot_eq; int incl_eq = block_scan_incl(eq, tot_eq, ws);
        int excl_eq = incl_eq - eq;
        int sel = gt | (eq & ((run_eq + excl_eq) < need_eq ? 1 : 0));
        int tot_sel; int incl_sel = block_scan_incl(sel, tot_sel, ws);
        if (i < n){
            if (sel){
                int idx = run_sel + incl_sel - 1;
                mapping[i] = idx;
                perm[idx] = i;
            } else mapping[i] = -1;
        }
        run_eq += tot_eq; run_sel += tot_sel;
    }
}

__global__ void compose_map_kernel()
{
    int i = blockIdx.x*blockDim.x + threadIdx.x;
    if (i < N0){ int m = g_map1[i]; g_map02[i] = (m >= 0) ? g_map2[m] : -1; }
}
__global__ void compose_perm_kernel()
{
    int j = blockIdx.x*blockDim.x + threadIdx.x;
    if (j < K2) g_perm02[j] = g_perm1[g_perm2[j]];
}

template<int C>
__global__ void unpool_kernel(const float* __restrict__ xb, const float* __restrict__ xs,
                              const int* __restrict__ mapping, float* __restrict__ out, int n)
{
    int idx = blockIdx.x*blockDim.x + threadIdx.x;
    int total = n * (C/4);
    if (idx >= total) return;
    int i = idx / (C/4), t = idx % (C/4);
    int m = mapping[i];
    float4 v = ((const float4*)(xb + (size_t)i*C))[t];
    if (m >= 0){
        float4 w = ((const float4*)(xs + (size_t)m*C))[t];
        v.x += w.x; v.y += w.y; v.z += w.z; v.w += w.w;
    }
    ((float4*)(out + (size_t)i*C))[t] = v;
}

// ---------------- final linear + log_softmax (warp per node) ----------------
__global__ void final_kernel(const float* __restrict__ x, const float* __restrict__ lw,
                             const float* __restrict__ lb, float* __restrict__ out, int n)
{
    int gw = blockIdx.x*(blockDim.x>>5) + (threadIdx.x>>5);
    int lane = threadIdx.x & 31;
    if (gw >= n) return;
    float4 xv = ((const float4*)(x + (size_t)gw*128))[lane];
    float lg[10]; float myv = 0.f;
    #pragma unroll
    for (int c = 0; c < 10; c++){
        float4 wv = ((const float4*)(lw + c*128))[lane];
        float p = xv.x*wv.x + xv.y*wv.y + xv.z*wv.z + xv.w*wv.w;
        #pragma unroll
        for (int off = 16; off; off >>= 1) p += __shfl_xor_sync(0xffffffffu, p, off);
        p += __ldg(&lb[c]);
        lg[c] = p;
        if (lane == c) myv = p;
    }
    float m = lg[0];
    #pragma unroll
    for (int c = 1; c < 10; c++) m = fmaxf(m, lg[c]);
    float s = 0.f;
    #pragma unroll
    for (int c = 0; c < 10; c++) s += expf(lg[c] - m);
    float lse = m + logf(s);
    if (lane < 10) out[(size_t)gw*10 + lane] = myv - lse;
}

// ---------------- host driver ----------------
extern "C" void kernel_launch(void* const* d_in, const int* in_sizes, int n_in,
                              void* d_out, int out_size)
{
    (void)in_sizes; (void)n_in; (void)out_size;
    const float* x    = (const float*)d_in[0];
    const int*   ei   = (const int*)d_in[1];
    const int*   src0 = ei;
    const int*   dst0 = ei + E0;
    const float *w1r=(const float*)d_in[2], *w1o=(const float*)d_in[3], *b1=(const float*)d_in[4], *p1w=(const float*)d_in[5];
    const float *w2r=(const float*)d_in[6], *w2o=(const float*)d_in[7], *b2=(const float*)d_in[8], *p2w=(const float*)d_in[9];
    const float *w3r=(const float*)d_in[10],*w3o=(const float*)d_in[11],*b3=(const float*)d_in[12];
    const float *w4r=(const float*)d_in[13],*w4o=(const float*)d_in[14],*b4=(const float*)d_in[15];
    const float *w5r=(const float*)d_in[16],*w5o=(const float*)d_in[17],*b5=(const float*)d_in[18];
    const float *lw =(const float*)d_in[19],*lb =(const float*)d_in[20];
    float* out = (float*)d_out;

    float *x1,*agg,*tbuf,*x2,*x3,*u1,*x4,*u2,*x5,*wT,*score;
    int *rowptr,*fill,*part,*partx,*map1,*perm1,*map2,*perm2,*map02,*perm02;
    cudaGetSymbolAddress((void**)&x1, g_x1);
    cudaGetSymbolAddress((void**)&agg, g_agg);
    cudaGetSymbolAddress((void**)&tbuf, g_t);
    cudaGetSymbolAddress((void**)&x2, g_x2);
    cudaGetSymbolAddress((void**)&x3, g_x3);
    cudaGetSymbolAddress((void**)&u1, g_u1);
    cudaGetSymbolAddress((void**)&x4, g_x4);
    cudaGetSymbolAddress((void**)&u2, g_u2);
    cudaGetSymbolAddress((void**)&x5, g_x5);
    cudaGetSymbolAddress((void**)&wT, g_wT);
    cudaGetSymbolAddress((void**)&score, g_score);
    cudaGetSymbolAddress((void**)&rowptr, g_rowptr);
    cudaGetSymbolAddress((void**)&fill, g_fill);
    cudaGetSymbolAddress((void**)&part, g_part);
    cudaGetSymbolAddress((void**)&partx, g_partx);
    cudaGetSymbolAddress((void**)&map1, g_map1);
    cudaGetSymbolAddress((void**)&perm1, g_perm1);
    cudaGetSymbolAddress((void**)&map2, g_map2);
    cudaGetSymbolAddress((void**)&perm2, g_perm2);
    cudaGetSymbolAddress((void**)&map02, g_map02);
    cudaGetSymbolAddress((void**)&perm02, g_perm02);

    const int W = 16384;

    cudaStream_t s2;
    cudaEvent_t ev1, ev2;
    cudaStreamCreateWithFlags(&s2, cudaStreamNonBlocking);
    cudaEventCreateWithFlags(&ev1, cudaEventDisableTiming);
    cudaEventCreateWithFlags(&ev2, cudaEventDisableTiming);

    // fork: CSR build + conv1 aggregation on s2
    cudaEventRecord(ev1, 0);
    cudaStreamWaitEvent(s2, ev1, 0);
    cudaMemsetAsync(fill, 0, N0*sizeof(int), s2);
    edge_count_kernel<<<(E0+255)/256,256,0,s2>>>(dst0);
    deg_reduce_kernel<<<NB_SCAN,1024,0,s2>>>(fill, part, N0);
    scan_kernel<<<1,1024,0,s2>>>(part, partx, NB_SCAN);
    deg_apply_kernel<<<NB_SCAN,1024,0,s2>>>(fill, partx, rowptr, N0);
    edge_scatter_kernel<<<(E0+255)/256,256,0,s2>>>(src0, dst0);
    agg_kernel<128><<<(N0+7)/8,256,0,s2>>>(x, agg, nullptr, nullptr, N0);
    cudaEventRecord(ev2, s2);

    // main: transposes + conv1 root-half GEMM (overlaps CSR+agg)
    {
        dim3 g(64, 10);
        transpose_all_kernel<<<g,256>>>(w1r,w1o,w2r,w2o,w3r,w3o,w4r,w4o,w5r,w5o, wT);
    }
    gemm_tc_kernel<128,128,false,false,false><<<(N0+127)/128,256>>>(
        x, nullptr, wT+1*W, nullptr, nullptr, nullptr, x1, N0, nullptr, nullptr);

    // join, then conv1 rel-half (in-place D add + bias + relu)
    cudaStreamWaitEvent(0, ev2, 0);
    gemm_tc_kernel<128,128,false,true,false><<<(N0+127)/128,256>>>(
        agg, nullptr, wT+0*W, nullptr, b1, x1, x1, N0, nullptr, nullptr);

    // pool1 (C=128, n=N0, k=K1)
    norm_kernel<128><<<1,32>>>(p1w);
    score_kernel<128><<<(N0+7)/8,256>>>(x1, p1w, N0);
    sel_init_kernel<<<1,256>>>(K1);
    for (int pass = 3; pass >= 0; pass--){
        sel_hist_kernel<<<(N0+255)/256,256>>>(N0, pass);
        sel_scan_kernel<<<1,256>>>(pass);
    }
    compact_kernel<<<1,1024>>>(map1, perm1, N0, K1);

    // conv2: 128 -> 64 on level 1 (gather+scale fused into GEMM A-loads)
    gemm_tc_kernel<64,128,false,false,true><<<(K1+127)/128,256>>>(
        x1, nullptr, wT+2*W, nullptr, nullptr, nullptr, tbuf, K1, perm1, score);
    agg_kernel<64><<<(K1+7)/8,256>>>(tbuf, agg, perm1, map1, K1);
    gemm_tc_kernel<64,128,false,true,true><<<(K1+127)/128,256>>>(
        x1, nullptr, wT+3*W, nullptr, b2, agg, x2, K1, perm1, score);

    // pool2 (C=64, n=K1, k=K2)
    norm_kernel<64><<<1,32>>>(p2w);
    score_kernel<64><<<(K1+7)/8,256>>>(x2, p2w, K1);
    sel_init_kernel<<<1,256>>>(K2);
    for (int pass = 3; pass >= 0; pass--){
        sel_hist_kernel<<<(K1+255)/256,256>>>(K1, pass);
        sel_scan_kernel<<<1,256>>>(pass);
    }
    compact_kernel<<<1,1024>>>(map2, perm2, K1, K2);

    // composed mappings level0 -> level2
    compose_map_kernel<<<(N0+255)/256,256>>>();
    compose_perm_kernel<<<(K2+255)/256,256>>>();

    // conv3: 64 -> 64 on level 2 (gather fused, transform-before-aggregate)
    gemm_tc_kernel<64,64,false,false,true><<<(K2+127)/128,256>>>(
        x2, nullptr, wT+4*W, nullptr, nullptr, nullptr, tbuf, K2, perm2, score);
    agg_kernel<64><<<(K2+7)/8,256>>>(tbuf, agg, perm02, map02, K2);
    gemm_tc_kernel<64,64,false,true,true><<<(K2+127)/128,256>>>(
        x2, nullptr, wT+5*W, nullptr, b3, agg, x3, K2, perm2, score);

    // unpool1 + skip: u1 = x2 + scatter(x3 via map2)
    unpool_kernel<64><<<(K1*16+255)/256,256>>>(x2, x3, map2, u1, K1);

    // conv4: 64 -> 128 on level 1
    agg_kernel<64><<<(K1+7)/8,256>>>(u1, agg, perm1, map1, K1);
    gemm_tc_kernel<128,64,true,true,false><<<(K1+127)/128,256>>>(
        agg, u1, wT+6*W, wT+7*W, b4, nullptr, x4, K1, nullptr, nullptr);

    // unpool2 + skip: u2 = x1 + scatter(x4 via map1)
    unpool_kernel<128><<<(N0*32+255)/256,256>>>(x1, x4, map1, u2, N0);

    // conv5: 128 -> 128 on level 0
    agg_kernel<128><<<(N0+7)/8,256>>>(u2, agg, nullptr, nullptr, N0);
    gemm_tc_kernel<128,128,true,true,false><<<(N0+127)/128,256>>>(
        agg, u2, wT+8*W, wT+9*W, b5, nullptr, x5, N0, nullptr, nullptr);

    // final linear + log_softmax
    final_kernel<<<(N0+7)/8,256>>>(x5, lw, lb, out, N0);
}

// round 6
// speedup vs baseline: 1.0874x; 1.0874x over previous
#include <cuda_runtime.h>
#include <cuda_bf16.h>
#include <math.h>

#define N0 50000
#define E0 1600000
#define K1 40000
#define K2 32000
#define NB_SCAN 49   // ceil(N0/1024)

// ---------------- scratch (device globals; no runtime allocation) ----------------
__device__ float g_x1[N0*128];
__device__ float g_agg[N0*128];
__device__ float g_t[K1*64];
__device__ float g_x2[K1*64];
__device__ float g_x3[K2*64];
__device__ float g_u1[K1*64];
__device__ float g_x4[K1*128];
__device__ float g_u2[N0*128];
__device__ float g_x5[N0*128];
__device__ int   g_rowptr[N0+1];
__device__ int   g_fill[N0];
__device__ int   g_part[64];
__device__ int   g_partx[66];
__device__ int   g_esrc[E0];
__device__ float g_score[N0];
__device__ unsigned g_key[N0];
__device__ int   g_map1[N0];
__device__ int   g_perm1[K1];
__device__ int   g_map2[K1];
__device__ int   g_perm2[K2];
__device__ int   g_map02[N0];
__device__ int   g_perm02[K2];
__device__ float g_wT[4*128*128];
__device__ unsigned g_hist[256];
__device__ unsigned g_prefix;
__device__ int   g_remaining;

// ---------------- CSR build ----------------
__global__ void zero_int_kernel(int* p, int n)
{
    int i = blockIdx.x*blockDim.x + threadIdx.x;
    if (i < n) p[i] = 0;
}

__global__ void edge_count_kernel(const int* __restrict__ dst)
{
    int e = blockIdx.x*blockDim.x + threadIdx.x;
    if (e < E0) atomicAdd(&g_fill[dst[e]], 1);
}

__device__ __forceinline__ int block_scan_incl(int val, int& total, int* ws)
{
    int lane = threadIdx.x & 31, wid = threadIdx.x >> 5;
    int x = val;
    #pragma unroll
    for (int off = 1; off < 32; off <<= 1){
        int y = __shfl_up_sync(0xffffffffu, x, off);
        if (lane >= off) x += y;
    }
    if (lane == 31) ws[wid] = x;
    __syncthreads();
    if (wid == 0){
        int s = ws[lane];
        #pragma unroll
        for (int off = 1; off < 32; off <<= 1){
            int y = __shfl_up_sync(0xffffffffu, s, off);
            if (lane >= off) s += y;
        }
        ws[lane] = s;
    }
    __syncthreads();
    int res = x + (wid ? ws[wid-1] : 0);
    total = ws[31];
    __syncthreads();
    return res;
}

__global__ void scan_kernel(const int* __restrict__ in, int* __restrict__ out, int n)
{
    __shared__ int ws[32];
    int run = 0;
    for (int base = 0; base < n; base += 1024){
        int i = base + threadIdx.x;
        int v = (i < n) ? in[i] : 0;
        int tot; int incl = block_scan_incl(v, tot, ws);
        if (i < n) out[i] = run + incl - v;
        run += tot;
    }
    if (threadIdx.x == 0) out[n] = run;
}

__global__ void deg_reduce_kernel(const int* __restrict__ in, int* __restrict__ part, int n)
{
    __shared__ int ws[32];
    int i = blockIdx.x*1024 + threadIdx.x;
    int v = (i < n) ? in[i] : 0;
    int lane = threadIdx.x & 31, wid = threadIdx.x >> 5;
    #pragma unroll
    for (int off = 16; off; off >>= 1) v += __shfl_down_sync(0xffffffffu, v, off);
    if (lane == 0) ws[wid] = v;
    __syncthreads();
    if (wid == 0){
        v = ws[lane];
        #pragma unroll
        for (int off = 16; off; off >>= 1) v += __shfl_down_sync(0xffffffffu, v, off);
        if (lane == 0) part[blockIdx.x] = v;
    }
}

__global__ void deg_apply_kernel(const int* __restrict__ in, const int* __restrict__ partx,
                                 int* __restrict__ rowptr, int n)
{
    __shared__ int ws[32];
    int i = blockIdx.x*1024 + threadIdx.x;
    int v = (i < n) ? in[i] : 0;
    int tot; int incl = block_scan_incl(v, tot, ws);
    if (i < n) rowptr[i] = partx[blockIdx.x] + incl - v;
    if (i == n) rowptr[n] = partx[gridDim.x];
}

__global__ void edge_scatter_kernel(const int* __restrict__ src, const int* __restrict__ dst)
{
    int e = blockIdx.x*blockDim.x + threadIdx.x;
    if (e < E0){
        int d = dst[e];
        int off = atomicSub(&g_fill[d], 1) - 1;
        g_esrc[g_rowptr[d] + off] = src[e];
    }
}

// ---------------- transpose of the 4 tf32-path weight matrices ----------------
__global__ void transpose_all_kernel(
    const float* w0, const float* w1, const float* w2, const float* w3,
    float* __restrict__ wT)
{
    const float* ws[4] = {w0,w1,w2,w3};
    const int CO[4] = {128,128,64,64};
    const int CI[4] = {128,128,128,128};
    int m = blockIdx.y;
    int idx = blockIdx.x*blockDim.x + threadIdx.x;
    int nEl = CO[m]*CI[m];
    if (idx < nEl){
        int r = idx / CI[m], c = idx % CI[m];
        wT[m*16384 + c*CO[m] + r] = ws[m][idx];
    }
}

// ---------------- aggregation: warp per node, vectorized row gather ----------------
template<int C>
__global__ void agg_kernel(const float* __restrict__ xin, float* __restrict__ out,
                           const int* __restrict__ perm, const int* __restrict__ mapping, int n)
{
    int warp = (blockIdx.x*blockDim.x + threadIdx.x) >> 5;
    int lane = threadIdx.x & 31;
    if (warp >= n) return;
    int old = perm ? perm[warp] : warp;
    int beg = g_rowptr[old], end = g_rowptr[old+1];
    if constexpr (C == 128){
        float4 acc = make_float4(0.f,0.f,0.f,0.f);
        for (int b = beg; b < end; b += 32){
            int e = b + lane;
            int s = -1;
            if (e < end){ s = g_esrc[e]; if (mapping) s = mapping[s]; }
            int cnt = min(32, end - b);
            for (int j = 0; j < cnt; j++){
                int sj = __shfl_sync(0xffffffffu, s, j);
                if (sj >= 0){
                    float4 v = ((const float4*)(xin + (size_t)sj*128))[lane];
                    acc.x += v.x; acc.y += v.y; acc.z += v.z; acc.w += v.w;
                }
            }
        }
        ((float4*)(out + (size_t)warp*128))[lane] = acc;
    } else {
        float2 acc = make_float2(0.f,0.f);
        for (int b = beg; b < end; b += 32){
            int e = b + lane;
            int s = -1;
            if (e < end){ s = g_esrc[e]; if (mapping) s = mapping[s]; }
            int cnt = min(32, end - b);
            for (int j = 0; j < cnt; j++){
                int sj = __shfl_sync(0xffffffffu, s, j);
                if (sj >= 0){
                    float2 v = ((const float2*)(xin + (size_t)sj*64))[lane];
                    acc.x += v.x; acc.y += v.y;
                }
            }
        }
        ((float2*)(out + (size_t)warp*64))[lane] = acc;
    }
}

// ---------------- tf32 split helpers ----------------
__device__ __forceinline__ void tf32_split(float a, float& hi, float& lo)
{
    unsigned h;
    asm("cvt.rna.tf32.f32 %0, %1;" : "=r"(h) : "f"(a));
    float hf = __uint_as_float(h);
    float l = a - hf;
    unsigned lu;
    asm("cvt.rna.tf32.f32 %0, %1;" : "=r"(lu) : "f"(l));
    hi = hf; lo = __uint_as_float(lu);
}

#define MMA_TF32(d, a0,a1,a2,a3, b0,b1) \
    asm volatile("mma.sync.aligned.m16n8k8.row.col.f32.tf32.tf32.f32 " \
        "{%0,%1,%2,%3}, {%4,%5,%6,%7}, {%8,%9}, {%0,%1,%2,%3};" \
        : "+f"((d)[0]), "+f"((d)[1]), "+f"((d)[2]), "+f"((d)[3]) \
        : "r"(a0), "r"(a1), "r"(a2), "r"(a3), "r"(b0), "r"(b1))

#define MMA_BF16(d, a0,a1,a2,a3, b0,b1) \
    asm volatile("mma.sync.aligned.m16n8k16.row.col.f32.bf16.bf16.f32 " \
        "{%0,%1,%2,%3}, {%4,%5,%6,%7}, {%8,%9}, {%0,%1,%2,%3};" \
        : "+f"((d)[0]), "+f"((d)[1]), "+f"((d)[2]), "+f"((d)[3]) \
        : "r"(a0), "r"(a1), "r"(a2), "r"(a3), "r"(b0), "r"(b1))

__device__ __forceinline__ unsigned short f2bf(float x)
{
    __nv_bfloat16 b = __float2bfloat16(x);
    return *reinterpret_cast<unsigned short*>(&b);
}
// split x = hi + lo (bf16 each); dropped lo*lo in products ~2^-16 relative
__device__ __forceinline__ void bf16_split(float x, unsigned short& hi, unsigned short& lo)
{
    __nv_bfloat16 h = __float2bfloat16(x);
    float hf = __bfloat162float(h);
    hi = *reinterpret_cast<unsigned short*>(&h);
    lo = f2bf(x - hf);
}

// ---------------- tf32 tensor-core GEMM (selection-critical layers) ----------------
template<int BN, int CIN, bool DUAL, bool RELU, bool GATHER>
__global__ void __launch_bounds__(256) gemm_tc_kernel(
    const float* __restrict__ A1, const float* __restrict__ A2,
    const float* __restrict__ W1, const float* __restrict__ W2,   // transposed [CIN][BN]
    const float* __restrict__ bias, const float* __restrict__ D,
    float* __restrict__ out, int n,
    const int* __restrict__ perm, const float* __restrict__ score)
{
    constexpr int BM = 128, BK = 16, TPB = 256;
    constexpr int BMp = 136, BNp = BN + 8;
    constexpr int AV = (BM*BK/4)/TPB;
    constexpr int BV = (BK*BN/4)/TPB;
    constexpr int TILES = CIN/BK;
    constexpr int T = (DUAL?2:1)*TILES;
    constexpr int MT = 2;
    constexpr int NT = BN/16;

    __shared__ float As[2][BK][BMp];
    __shared__ float Bs[2][BK][BNp];

    int tid = threadIdx.x, lane = tid & 31, warp = tid >> 5;
    int m0 = (warp >> 1) * 32;
    int n0 = (warp & 1) * (BN/2);
    int row0 = blockIdx.x * BM;
    int gid = lane >> 2, tig = lane & 3;

    int am[AV], akq[AV], aar[AV]; float asc[AV];
    #pragma unroll
    for (int u = 0; u < AV; u++){
        int f = tid + u*TPB;
        am[u] = f >> 2; akq[u] = (f & 3) << 2;
        int r = row0 + am[u];
        aar[u] = -1; asc[u] = 1.f;
        if (r < n){
            int ar = r;
            if (GATHER){ ar = perm[r]; asc[u] = score[ar]; }
            aar[u] = ar;
        }
    }
    int bkk[BV], bc4[BV];
    #pragma unroll
    for (int u = 0; u < BV; u++){
        int f = tid + u*TPB;
        bkk[u] = f / (BN/4); bc4[u] = (f % (BN/4)) << 2;
    }

    float4 ra[AV], rb[BV];
    auto load_tile = [&](int t){
        int ph = DUAL ? (t / TILES) : 0;
        int k0 = (t % TILES) * BK;
        const float* A = (DUAL && ph) ? A2 : A1;
        const float* W = (DUAL && ph) ? W2 : W1;
        #pragma unroll
        for (int u = 0; u < AV; u++){
            float4 v = make_float4(0.f,0.f,0.f,0.f);
            if (aar[u] >= 0){
                v = *(const float4*)(A + (size_t)aar[u]*CIN + k0 + akq[u]);
                if (GATHER){ v.x*=asc[u]; v.y*=asc[u]; v.z*=asc[u]; v.w*=asc[u]; }
            }
            ra[u] = v;
        }
        #pragma unroll
        for (int u = 0; u < BV; u++)
            rb[u] = *(const float4*)(W + (size_t)(k0 + bkk[u])*BN + bc4[u]);
    };
    auto store_split = [&](){
        #pragma unroll
        for (int u = 0; u < AV; u++){
            const float* s = (const float*)&ra[u];
            #pragma unroll
            for (int q = 0; q < 4; q++){
                float hi, lo; tf32_split(s[q], hi, lo);
                As[0][akq[u]+q][am[u]] = hi;
                As[1][akq[u]+q][am[u]] = lo;
            }
        }
        #pragma unroll
        for (int u = 0; u < BV; u++){
            const float* s = (const float*)&rb[u];
            #pragma unroll
            for (int q = 0; q < 4; q++){
                float hi, lo; tf32_split(s[q], hi, lo);
                Bs[0][bkk[u]][bc4[u]+q] = hi;
                Bs[1][bkk[u]][bc4[u]+q] = lo;
            }
        }
    };

    float acc[MT][NT][4];
    #pragma unroll
    for (int mi = 0; mi < MT; mi++)
        #pragma unroll
        for (int ni = 0; ni < NT; ni++)
            #pragma unroll
            for (int q = 0; q < 4; q++) acc[mi][ni][q] = 0.f;

    load_tile(0);
    for (int t = 0; t < T; t++){
        store_split();
        __syncthreads();
        if (t + 1 < T) load_tile(t + 1);
        #pragma unroll
        for (int kk = 0; kk < 2; kk++){
            int ko = kk * 8;
            unsigned ah[MT][4], al[MT][4];
            #pragma unroll
            for (int mi = 0; mi < MT; mi++){
                int mb = m0 + mi*16 + gid;
                ah[mi][0] = __float_as_uint(As[0][ko+tig  ][mb  ]);
                ah[mi][1] = __float_as_uint(As[0][ko+tig  ][mb+8]);
                ah[mi][2] = __float_as_uint(As[0][ko+tig+4][mb  ]);
                ah[mi][3] = __float_as_uint(As[0][ko+tig+4][mb+8]);
                al[mi][0] = __float_as_uint(As[1][ko+tig  ][mb  ]);
                al[mi][1] = __float_as_uint(As[1][ko+tig  ][mb+8]);
                al[mi][2] = __float_as_uint(As[1][ko+tig+4][mb  ]);
                al[mi][3] = __float_as_uint(As[1][ko+tig+4][mb+8]);
            }
            #pragma unroll
            for (int ni = 0; ni < NT; ni++){
                int nb = n0 + ni*8 + gid;
                unsigned bh0 = __float_as_uint(Bs[0][ko+tig  ][nb]);
                unsigned bh1 = __float_as_uint(Bs[0][ko+tig+4][nb]);
                unsigned bl0 = __float_as_uint(Bs[1][ko+tig  ][nb]);
                unsigned bl1 = __float_as_uint(Bs[1][ko+tig+4][nb]);
                #pragma unroll
                for (int mi = 0; mi < MT; mi++){
                    MMA_TF32(acc[mi][ni], ah[mi][0],ah[mi][1],ah[mi][2],ah[mi][3], bh0,bh1);
                    MMA_TF32(acc[mi][ni], ah[mi][0],ah[mi][1],ah[mi][2],ah[mi][3], bl0,bl1);
                    MMA_TF32(acc[mi][ni], al[mi][0],al[mi][1],al[mi][2],al[mi][3], bh0,bh1);
                }
            }
        }
        __syncthreads();
    }

    #pragma unroll
    for (int mi = 0; mi < MT; mi++){
        #pragma unroll
        for (int ni = 0; ni < NT; ni++){
            int cc = n0 + ni*8 + tig*2;
            #pragma unroll
            for (int h = 0; h < 2; h++){
                int rr = row0 + m0 + mi*16 + gid + h*8;
                if (rr < n){
                    float v0 = acc[mi][ni][h*2+0];
                    float v1 = acc[mi][ni][h*2+1];
                    if (bias){ v0 += __ldg(&bias[cc]); v1 += __ldg(&bias[cc+1]); }
                    if (D){ v0 += D[(size_t)rr*BN + cc]; v1 += D[(size_t)rr*BN + cc + 1]; }
                    if (RELU){ v0 = fmaxf(v0, 0.f); v1 = fmaxf(v1, 0.f); }
                    *(float2*)(out + (size_t)rr*BN + cc) = make_float2(v0, v1);
                }
            }
        }
    }
}

// ---------------- bf16-split tensor-core GEMM (selection-independent layers) ----------------
// A [m][k] fp32, W original layout [BN][CIN] fp32 (no transpose needed).
// x = hi + lo (bf16); 3-term products; dropped lo*lo ~ 2^-16 relative.
// m16n8k16 frags: a0={A[g][2t],A[g][2t+1]}, a1=row g+8, a2=cols+8, a3=row+8,cols+8;
//                 b0={B[2t][g],B[2t+1][g]}, b1=rows+8.
template<int BN, int CIN, bool DUAL, bool RELU, bool GATHER>
__global__ void __launch_bounds__(256) gemm_bf16_kernel(
    const float* __restrict__ A1, const float* __restrict__ A2,
    const float* __restrict__ W1, const float* __restrict__ W2,
    const float* __restrict__ bias, const float* __restrict__ D,
    float* __restrict__ out, int n,
    const int* __restrict__ perm, const float* __restrict__ score)
{
    constexpr int BM = 128, BK = 32, TPB = 256;
    constexpr int STR = 20;                       // words per row; 20 ≡ 4 mod 32 -> conflict-free frags
    constexpr int AV = (BM*BK/4)/TPB;             // 4 float4 per thread
    constexpr int BV = (BN*BK/4)/TPB;             // 4 (BN=128) / 2 (BN=64)
    constexpr int TILES = CIN/BK;
    constexpr int T = (DUAL?2:1)*TILES;
    constexpr int MT = 2;
    constexpr int NT = BN/16;

    __shared__ unsigned As[2][BM][STR];           // [hi/lo][m][k-pair word]
    __shared__ unsigned Bs[2][BN][STR];           // [hi/lo][n][k-pair word]

    int tid = threadIdx.x, lane = tid & 31, warp = tid >> 5;
    int m0 = (warp >> 1) * 32;
    int n0 = (warp & 1) * (BN/2);
    int row0 = blockIdx.x * BM;
    int gid = lane >> 2, tig = lane & 3;

    // A geometry: f covers (row, 4 consecutive k)
    int am[AV], akq[AV], aar[AV]; float asc[AV];
    #pragma unroll
    for (int u = 0; u < AV; u++){
        int f = tid + u*TPB;
        am[u] = f >> 3; akq[u] = (f & 7) << 2;
        int r = row0 + am[u];
        aar[u] = -1; asc[u] = 1.f;
        if (r < n){
            int ar = r;
            if (GATHER){ ar = perm[r]; asc[u] = score[ar]; }
            aar[u] = ar;
        }
    }
    int bm[BV], bkq[BV];
    #pragma unroll
    for (int u = 0; u < BV; u++){
        int f = tid + u*TPB;
        bm[u] = f >> 3; bkq[u] = (f & 7) << 2;
    }

    float4 ra[AV], rb[BV];
    auto load_tile = [&](int t){
        int ph = DUAL ? (t / TILES) : 0;
        int k0 = (t % TILES) * BK;
        const float* A = (DUAL && ph) ? A2 : A1;
        const float* W = (DUAL && ph) ? W2 : W1;
        #pragma unroll
        for (int u = 0; u < AV; u++){
            float4 v = make_float4(0.f,0.f,0.f,0.f);
            if (aar[u] >= 0){
                v = *(const float4*)(A + (size_t)aar[u]*CIN + k0 + akq[u]);
                if (GATHER){ v.x*=asc[u]; v.y*=asc[u]; v.z*=asc[u]; v.w*=asc[u]; }
            }
            ra[u] = v;
        }
        #pragma unroll
        for (int u = 0; u < BV; u++)
            rb[u] = *(const float4*)(W + (size_t)bm[u]*CIN + k0 + bkq[u]);
    };
    auto store_split = [&](){
        #pragma unroll
        for (int u = 0; u < AV; u++){
            const float* s = (const float*)&ra[u];
            unsigned short h0,l0,h1,l1,h2,l2,h3,l3;
            bf16_split(s[0],h0,l0); bf16_split(s[1],h1,l1);
            bf16_split(s[2],h2,l2); bf16_split(s[3],h3,l3);
            int w = akq[u] >> 1;
            As[0][am[u]][w  ] = (unsigned)h0 | ((unsigned)h1 << 16);
            As[0][am[u]][w+1] = (unsigned)h2 | ((unsigned)h3 << 16);
            As[1][am[u]][w  ] = (unsigned)l0 | ((unsigned)l1 << 16);
            As[1][am[u]][w+1] = (unsigned)l2 | ((unsigned)l3 << 16);
        }
        #pragma unroll
        for (int u = 0; u < BV; u++){
            const float* s = (const float*)&rb[u];
            unsigned short h0,l0,h1,l1,h2,l2,h3,l3;
            bf16_split(s[0],h0,l0); bf16_split(s[1],h1,l1);
            bf16_split(s[2],h2,l2); bf16_split(s[3],h3,l3);
            int w = bkq[u] >> 1;
            Bs[0][bm[u]][w  ] = (unsigned)h0 | ((unsigned)h1 << 16);
            Bs[0][bm[u]][w+1] = (unsigned)h2 | ((unsigned)h3 << 16);
            Bs[1][bm[u]][w  ] = (unsigned)l0 | ((unsigned)l1 << 16);
            Bs[1][bm[u]][w+1] = (unsigned)l2 | ((unsigned)l3 << 16);
        }
    };

    float acc[MT][NT][4];
    #pragma unroll
    for (int mi = 0; mi < MT; mi++)
        #pragma unroll
        for (int ni = 0; ni < NT; ni++)
            #pragma unroll
            for (int q = 0; q < 4; q++) acc[mi][ni][q] = 0.f;

    load_tile(0);
    for (int t = 0; t < T; t++){
        store_split();
        __syncthreads();
        if (t + 1 < T) load_tile(t + 1);
        #pragma unroll
        for (int kk = 0; kk < 2; kk++){       // two k16 steps per BK=32 tile
            int ko = kk * 8;                   // word offset
            unsigned ah[MT][4], al[MT][4];
            #pragma unroll
            for (int mi = 0; mi < MT; mi++){
                int mb = m0 + mi*16 + gid;
                ah[mi][0] = As[0][mb  ][ko+tig  ];
                ah[mi][1] = As[0][mb+8][ko+tig  ];
                ah[mi][2] = As[0][mb  ][ko+tig+4];
                ah[mi][3] = As[0][mb+8][ko+tig+4];
                al[mi][0] = As[1][mb  ][ko+tig  ];
                al[mi][1] = As[1][mb+8][ko+tig  ];
                al[mi][2] = As[1][mb  ][ko+tig+4];
                al[mi][3] = As[1][mb+8][ko+tig+4];
            }
            #pragma unroll
            for (int ni = 0; ni < NT; ni++){
                int nb = n0 + ni*8 + gid;
                unsigned bh0 = Bs[0][nb][ko+tig  ];
                unsigned bh1 = Bs[0][nb][ko+tig+4];
                unsigned bl0 = Bs[1][nb][ko+tig  ];
                unsigned bl1 = Bs[1][nb][ko+tig+4];
                #pragma unroll
                for (int mi = 0; mi < MT; mi++){
                    MMA_BF16(acc[mi][ni], ah[mi][0],ah[mi][1],ah[mi][2],ah[mi][3], bh0,bh1);
                    MMA_BF16(acc[mi][ni], ah[mi][0],ah[mi][1],ah[mi][2],ah[mi][3], bl0,bl1);
                    MMA_BF16(acc[mi][ni], al[mi][0],al[mi][1],al[mi][2],al[mi][3], bh0,bh1);
                }
            }
        }
        __syncthreads();
    }

    #pragma unroll
    for (int mi = 0; mi < MT; mi++){
        #pragma unroll
        for (int ni = 0; ni < NT; ni++){
            int cc = n0 + ni*8 + tig*2;
            #pragma unroll
            for (int h = 0; h < 2; h++){
                int rr = row0 + m0 + mi*16 + gid + h*8;
                if (rr < n){
                    float v0 = acc[mi][ni][h*2+0];
                    float v1 = acc[mi][ni][h*2+1];
                    if (bias){ v0 += __ldg(&bias[cc]); v1 += __ldg(&bias[cc+1]); }
                    if (D){ v0 += D[(size_t)rr*BN + cc]; v1 += D[(size_t)rr*BN + cc + 1]; }
                    if (RELU){ v0 = fmaxf(v0, 0.f); v1 = fmaxf(v1, 0.f); }
                    *(float2*)(out + (size_t)rr*BN + cc) = make_float2(v0, v1);
                }
            }
        }
    }
}

// ---------------- topk pooling ----------------
template<int C>
__global__ void score_kernel(const float* __restrict__ x, const float* __restrict__ w, int n)
{
    int gw = blockIdx.x*(blockDim.x>>5) + (threadIdx.x>>5);
    int lane = threadIdx.x & 31;
    if (gw >= n) return;
    float p, q;
    if constexpr (C == 128){
        float4 xv = ((const float4*)(x + (size_t)gw*128))[lane];
        float4 wv = ((const float4*)w)[lane];
        p = xv.x*wv.x + xv.y*wv.y + xv.z*wv.z + xv.w*wv.w;
        q = wv.x*wv.x + wv.y*wv.y + wv.z*wv.z + wv.w*wv.w;
    } else {
        float2 xv = ((const float2*)(x + (size_t)gw*64))[lane];
        float2 wv = ((const float2*)w)[lane];
        p = xv.x*wv.x + xv.y*wv.y;
        q = wv.x*wv.x + wv.y*wv.y;
    }
    #pragma unroll
    for (int off = 16; off; off >>= 1){
        p += __shfl_xor_sync(0xffffffffu, p, off);
        q += __shfl_xor_sync(0xffffffffu, q, off);
    }
    if (lane == 0){
        float s = tanhf(p / sqrtf(q));
        g_score[gw] = s;
        unsigned u = __float_as_uint(s);
        u = (u & 0x80000000u) ? ~u : (u | 0x80000000u);
        g_key[gw] = u;
    }
}

__global__ void sel_init_kernel(int k)
{
    int t = threadIdx.x;
    if (t < 256) g_hist[t] = 0;
    if (t == 0){ g_prefix = 0; g_remaining = k; }
}

__global__ void sel_hist_kernel(int n, int pass)
{
    __shared__ unsigned sh[256];
    for (int t = threadIdx.x; t < 256; t += blockDim.x) sh[t] = 0;
    __syncthreads();
    int i = blockIdx.x*blockDim.x + threadIdx.x;
    if (i < n){
        unsigned key = g_key[i];
        bool ok;
        if (pass == 3) ok = true;
        else { int shf = (pass+1)*8; ok = ((key >> shf) == (g_prefix >> shf)); }
        if (ok) atomicAdd(&sh[(key >> (pass*8)) & 255], 1u);
    }
    __syncthreads();
    for (int t = threadIdx.x; t < 256; t += blockDim.x){
        unsigned v = sh[t]; if (v) atomicAdd(&g_hist[t], v);
    }
}

__global__ void sel_scan_kernel(int pass)
{
    if (threadIdx.x == 0){
        unsigned r = (unsigned)g_remaining;
        unsigned c = 0; int b = 255;
        for (; b > 0; b--){
            unsigned h = g_hist[b];
            if (c + h >= r) break;
            c += h;
        }
        g_prefix |= ((unsigned)b) << (pass*8);
        g_remaining = (int)(r - c);
    }
    __syncthreads();
    for (int t = threadIdx.x; t < 256; t += blockDim.x) g_hist[t] = 0;
}

__global__ void compact_kernel(int* __restrict__ mapping, int* __restrict__ perm, int n, int k)
{
    __shared__ int ws[32];
    unsigned thr = g_prefix;
    int local = 0;
    for (int base = 0; base < n; base += 1024){
        int i = base + threadIdx.x;
        if (i < n) local += (g_key[i] > thr) ? 1 : 0;
    }
    int totG; block_scan_incl(local, totG, ws);
    int need_eq = k - totG;
    int run_eq = 0, run_sel = 0;
    for (int base = 0; base < n; base += 1024){
        int i = base + threadIdx.x;
        int gt = 0, eq = 0;
        if (i < n){
            unsigned kv = g_key[i];
            gt = (kv > thr); eq = (kv == thr);
        }
        int tot_eq; int incl_eq = block_scan_incl(eq, tot_eq, ws);
        int excl_eq = incl_eq - eq;
        int sel = gt | (eq & ((run_eq + excl_eq) < need_eq ? 1 : 0));
        int tot_sel; int incl_sel = block_scan_incl(sel, tot_sel, ws);
        if (i < n){
            if (sel){
                int idx = run_sel + incl_sel - 1;
                mapping[i] = idx;
                perm[idx] = i;
            } else mapping[i] = -1;
        }
        run_eq += tot_eq; run_sel += tot_sel;
    }
}

__global__ void compose_map_kernel()
{
    int i = blockIdx.x*blockDim.x + threadIdx.x;
    if (i < N0){ int m = g_map1[i]; g_map02[i] = (m >= 0) ? g_map2[m] : -1; }
}
__global__ void compose_perm_kernel()
{
    int j = blockIdx.x*blockDim.x + threadIdx.x;
    if (j < K2) g_perm02[j] = g_perm1[g_perm2[j]];
}

template<int C>
__global__ void unpool_kernel(const float* __restrict__ xb, const float* __restrict__ xs,
                              const int* __restrict__ mapping, float* __restrict__ out, int n)
{
    int idx = blockIdx.x*blockDim.x + threadIdx.x;
    int total = n * (C/4);
    if (idx >= total) return;
    int i = idx / (C/4), t = idx % (C/4);
    int m = mapping[i];
    float4 v = ((const float4*)(xb + (size_t)i*C))[t];
    if (m >= 0){
        float4 w = ((const float4*)(xs + (size_t)m*C))[t];
        v.x += w.x; v.y += w.y; v.z += w.z; v.w += w.w;
    }
    ((float4*)(out + (size_t)i*C))[t] = v;
}

// ---------------- final linear + log_softmax (warp per node) ----------------
__global__ void final_kernel(const float* __restrict__ x, const float* __restrict__ lw,
                             const float* __restrict__ lb, float* __restrict__ out, int n)
{
    int gw = blockIdx.x*(blockDim.x>>5) + (threadIdx.x>>5);
    int lane = threadIdx.x & 31;
    if (gw >= n) return;
    float4 xv = ((const float4*)(x + (size_t)gw*128))[lane];
    float lg[10]; float myv = 0.f;
    #pragma unroll
    for (int c = 0; c < 10; c++){
        float4 wv = ((const float4*)(lw + c*128))[lane];
        float p = xv.x*wv.x + xv.y*wv.y + xv.z*wv.z + xv.w*wv.w;
        #pragma unroll
        for (int off = 16; off; off >>= 1) p += __shfl_xor_sync(0xffffffffu, p, off);
        p += __ldg(&lb[c]);
        lg[c] = p;
        if (lane == c) myv = p;
    }
    float m = lg[0];
    #pragma unroll
    for (int c = 1; c < 10; c++) m = fmaxf(m, lg[c]);
    float s = 0.f;
    #pragma unroll
    for (int c = 0; c < 10; c++) s += expf(lg[c] - m);
    float lse = m + logf(s);
    if (lane < 10) out[(size_t)gw*10 + lane] = myv - lse;
}

// ---------------- host driver ----------------
extern "C" void kernel_launch(void* const* d_in, const int* in_sizes, int n_in,
                              void* d_out, int out_size)
{
    (void)in_sizes; (void)n_in; (void)out_size;
    const float* x    = (const float*)d_in[0];
    const int*   ei   = (const int*)d_in[1];
    const int*   src0 = ei;
    const int*   dst0 = ei + E0;
    const float *w1r=(const float*)d_in[2], *w1o=(const float*)d_in[3], *b1=(const float*)d_in[4], *p1w=(const float*)d_in[5];
    const float *w2r=(const float*)d_in[6], *w2o=(const float*)d_in[7], *b2=(const float*)d_in[8], *p2w=(const float*)d_in[9];
    const float *w3r=(const float*)d_in[10],*w3o=(const float*)d_in[11],*b3=(const float*)d_in[12];
    const float *w4r=(const float*)d_in[13],*w4o=(const float*)d_in[14],*b4=(const float*)d_in[15];
    const float *w5r=(const float*)d_in[16],*w5o=(const float*)d_in[17],*b5=(const float*)d_in[18];
    const float *lw =(const float*)d_in[19],*lb =(const float*)d_in[20];
    float* out = (float*)d_out;

    float *x1,*agg,*tbuf,*x2,*x3,*u1,*x4,*u2,*x5,*wT,*score;
    int *rowptr,*fill,*part,*partx,*map1,*perm1,*map2,*perm2,*map02,*perm02;
    cudaGetSymbolAddress((void**)&x1, g_x1);
    cudaGetSymbolAddress((void**)&agg, g_agg);
    cudaGetSymbolAddress((void**)&tbuf, g_t);
    cudaGetSymbolAddress((void**)&x2, g_x2);
    cudaGetSymbolAddress((void**)&x3, g_x3);
    cudaGetSymbolAddress((void**)&u1, g_u1);
    cudaGetSymbolAddress((void**)&x4, g_x4);
    cudaGetSymbolAddress((void**)&u2, g_u2);
    cudaGetSymbolAddress((void**)&x5, g_x5);
    cudaGetSymbolAddress((void**)&wT, g_wT);
    cudaGetSymbolAddress((void**)&score, g_score);
    cudaGetSymbolAddress((void**)&rowptr, g_rowptr);
    cudaGetSymbolAddress((void**)&fill, g_fill);
    cudaGetSymbolAddress((void**)&part, g_part);
    cudaGetSymbolAddress((void**)&partx, g_partx);
    cudaGetSymbolAddress((void**)&map1, g_map1);
    cudaGetSymbolAddress((void**)&perm1, g_perm1);
    cudaGetSymbolAddress((void**)&map2, g_map2);
    cudaGetSymbolAddress((void**)&perm2, g_perm2);
    cudaGetSymbolAddress((void**)&map02, g_map02);
    cudaGetSymbolAddress((void**)&perm02, g_perm02);

    const int W = 16384;

    // single stream; launch order puts the first tf32 GEMM at slot 6 for ncu (-s 5 -c 1)
    {
        dim3 g(64, 4);
        transpose_all_kernel<<<g,256>>>(w1r,w1o,w2r,w2o, wT);            // 1
    }
    zero_int_kernel<<<(N0+255)/256,256>>>(fill, N0);                     // 2
    edge_count_kernel<<<(E0+255)/256,256>>>(dst0);                       // 3
    deg_reduce_kernel<<<NB_SCAN,1024>>>(fill, part, N0);                 // 4
    scan_kernel<<<1,1024>>>(part, partx, NB_SCAN);                       // 5
    gemm_tc_kernel<128,128,false,false,false><<<(N0+127)/128,256>>>(     // 6 (profiled)
        x, nullptr, wT+1*W, nullptr, nullptr, nullptr, x1, N0, nullptr, nullptr);
    deg_apply_kernel<<<NB_SCAN,1024>>>(fill, partx, rowptr, N0);         // 7
    edge_scatter_kernel<<<(E0+255)/256,256>>>(src0, dst0);               // 8
    agg_kernel<128><<<(N0+7)/8,256>>>(x, agg, nullptr, nullptr, N0);     // 9

    // conv1 rel-half (in-place D add + bias + relu)
    gemm_tc_kernel<128,128,false,true,false><<<(N0+127)/128,256>>>(
        agg, nullptr, wT+0*W, nullptr, b1, x1, x1, N0, nullptr, nullptr);

    // pool1
    score_kernel<128><<<(N0+7)/8,256>>>(x1, p1w, N0);
    sel_init_kernel<<<1,256>>>(K1);
    for (int pass = 3; pass >= 0; pass--){
        sel_hist_kernel<<<(N0+255)/256,256>>>(N0, pass);
        sel_scan_kernel<<<1,256>>>(pass);
    }
    compact_kernel<<<1,1024>>>(map1, perm1, N0, K1);

    // conv2: 128 -> 64 on level 1 (tf32; feeds pool2 scores)
    gemm_tc_kernel<64,128,false,false,true><<<(K1+127)/128,256>>>(
        x1, nullptr, wT+2*W, nullptr, nullptr, nullptr, tbuf, K1, perm1, score);
    agg_kernel<64><<<(K1+7)/8,256>>>(tbuf, agg, perm1, map1, K1);
    gemm_tc_kernel<64,128,false,true,true><<<(K1+127)/128,256>>>(
        x1, nullptr, wT+3*W, nullptr, b2, agg, x2, K1, perm1, score);

    // pool2
    score_kernel<64><<<(K1+7)/8,256>>>(x2, p2w, K1);
    sel_init_kernel<<<1,256>>>(K2);
    for (int pass = 3; pass >= 0; pass--){
        sel_hist_kernel<<<(K1+255)/256,256>>>(K1, pass);
        sel_scan_kernel<<<1,256>>>(pass);
    }
    compact_kernel<<<1,1024>>>(map2, perm2, K1, K2);

    // composed mappings level0 -> level2
    compose_map_kernel<<<(N0+255)/256,256>>>();
    compose_perm_kernel<<<(K2+255)/256,256>>>();

    // conv3: 64 -> 64 on level 2 (bf16-split; selection-independent)
    gemm_bf16_kernel<64,64,false,false,true><<<(K2+127)/128,256>>>(
        x2, nullptr, w3r, nullptr, nullptr, nullptr, tbuf, K2, perm2, score);
    agg_kernel<64><<<(K2+7)/8,256>>>(tbuf, agg, perm02, map02, K2);
    gemm_bf16_kernel<64,64,false,true,true><<<(K2+127)/128,256>>>(
        x2, nullptr, w3o, nullptr, b3, agg, x3, K2, perm2, score);

    // unpool1 + skip
    unpool_kernel<64><<<(K1*16+255)/256,256>>>(x2, x3, map2, u1, K1);

    // conv4: 64 -> 128 on level 1 (bf16-split)
    agg_kernel<64><<<(K1+7)/8,256>>>(u1, agg, perm1, map1, K1);
    gemm_bf16_kernel<128,64,true,true,false><<<(K1+127)/128,256>>>(
        agg, u1, w4r, w4o, b4, nullptr, x4, K1, nullptr, nullptr);

    // unpool2 + skip
    unpool_kernel<128><<<(N0*32+255)/256,256>>>(x1, x4, map1, u2, N0);

    // conv5: 128 -> 128 on level 0 (bf16-split)
    agg_kernel<128><<<(N0+7)/8,256>>>(u2, agg, nullptr, nullptr, N0);
    gemm_bf16_kernel<128,128,true,true,false><<<(N0+127)/128,256>>>(
        agg, u2, w5r, w5o, b5, nullptr, x5, N0, nullptr, nullptr);

    // final linear + log_softmax
    final_kernel<<<(N0+7)/8,256>>>(x5, lw, lb, out, N0);
}

// round 7
// speedup vs baseline: 1.1250x; 1.0345x over previous
#include <cuda_runtime.h>
#include <cuda_bf16.h>
#include <math.h>

#define N0 50000
#define E0 1600000
#define K1 40000
#define K2 32000
#define NB_SCAN 49   // ceil(N0/1024)

// ---------------- scratch (device globals; no runtime allocation) ----------------
__device__ float g_x1[N0*128];
__device__ float g_agg[N0*128];
__device__ float g_t[K1*64];
__device__ float g_x2[K1*64];
__device__ float g_x3[K2*64];
__device__ float g_u1[K1*64];
__device__ float g_x4[K1*128];
__device__ float g_u2[N0*128];
__device__ float g_x5[N0*128];
__device__ int   g_rowptr[N0+1];
__device__ int   g_fill[N0];
__device__ int   g_part[64];
__device__ int   g_partx[66];
__device__ int   g_esrc[E0];
__device__ float g_score[N0];
__device__ unsigned g_key[N0];
__device__ int   g_map1[N0];
__device__ int   g_perm1[K1];
__device__ int   g_map2[K1];
__device__ int   g_perm2[K2];
__device__ int   g_map02[N0];
__device__ int   g_perm02[K2];
__device__ float g_wT[4*128*128];

// ---------------- CSR build ----------------
__global__ void zero_int_kernel(int* p, int n)
{
    int i = blockIdx.x*blockDim.x + threadIdx.x;
    if (i < n) p[i] = 0;
}

__global__ void edge_count_kernel(const int* __restrict__ dst)
{
    int e = blockIdx.x*blockDim.x + threadIdx.x;
    if (e < E0) atomicAdd(&g_fill[dst[e]], 1);
}

__device__ __forceinline__ int block_scan_incl(int val, int& total, int* ws)
{
    int lane = threadIdx.x & 31, wid = threadIdx.x >> 5;
    int x = val;
    #pragma unroll
    for (int off = 1; off < 32; off <<= 1){
        int y = __shfl_up_sync(0xffffffffu, x, off);
        if (lane >= off) x += y;
    }
    if (lane == 31) ws[wid] = x;
    __syncthreads();
    if (wid == 0){
        int s = ws[lane];
        #pragma unroll
        for (int off = 1; off < 32; off <<= 1){
            int y = __shfl_up_sync(0xffffffffu, s, off);
            if (lane >= off) s += y;
        }
        ws[lane] = s;
    }
    __syncthreads();
    int res = x + (wid ? ws[wid-1] : 0);
    total = ws[31];
    __syncthreads();
    return res;
}

__global__ void scan_kernel(const int* __restrict__ in, int* __restrict__ out, int n)
{
    __shared__ int ws[32];
    int run = 0;
    for (int base = 0; base < n; base += 1024){
        int i = base + threadIdx.x;
        int v = (i < n) ? in[i] : 0;
        int tot; int incl = block_scan_incl(v, tot, ws);
        if (i < n) out[i] = run + incl - v;
        run += tot;
    }
    if (threadIdx.x == 0) out[n] = run;
}

__global__ void deg_reduce_kernel(const int* __restrict__ in, int* __restrict__ part, int n)
{
    __shared__ int ws[32];
    int i = blockIdx.x*1024 + threadIdx.x;
    int v = (i < n) ? in[i] : 0;
    int lane = threadIdx.x & 31, wid = threadIdx.x >> 5;
    #pragma unroll
    for (int off = 16; off; off >>= 1) v += __shfl_down_sync(0xffffffffu, v, off);
    if (lane == 0) ws[wid] = v;
    __syncthreads();
    if (wid == 0){
        v = ws[lane];
        #pragma unroll
        for (int off = 16; off; off >>= 1) v += __shfl_down_sync(0xffffffffu, v, off);
        if (lane == 0) part[blockIdx.x] = v;
    }
}

__global__ void deg_apply_kernel(const int* __restrict__ in, const int* __restrict__ partx,
                                 int* __restrict__ rowptr, int n)
{
    __shared__ int ws[32];
    int i = blockIdx.x*1024 + threadIdx.x;
    int v = (i < n) ? in[i] : 0;
    int tot; int incl = block_scan_incl(v, tot, ws);
    if (i < n) rowptr[i] = partx[blockIdx.x] + incl - v;
    if (i == n) rowptr[n] = partx[gridDim.x];
}

__global__ void edge_scatter_kernel(const int* __restrict__ src, const int* __restrict__ dst)
{
    int e = blockIdx.x*blockDim.x + threadIdx.x;
    if (e < E0){
        int d = dst[e];
        int off = atomicSub(&g_fill[d], 1) - 1;
        g_esrc[g_rowptr[d] + off] = src[e];
    }
}

// ---------------- transpose of the 4 tf32-path weight matrices ----------------
__global__ void transpose_all_kernel(
    const float* w0, const float* w1, const float* w2, const float* w3,
    float* __restrict__ wT)
{
    const float* ws[4] = {w0,w1,w2,w3};
    const int CO[4] = {128,128,64,64};
    const int CI[4] = {128,128,128,128};
    int m = blockIdx.y;
    int idx = blockIdx.x*blockDim.x + threadIdx.x;
    int nEl = CO[m]*CI[m];
    if (idx < nEl){
        int r = idx / CI[m], c = idx % CI[m];
        wT[m*16384 + c*CO[m] + r] = ws[m][idx];
    }
}

// ---------------- aggregation: warp per node, vectorized row gather ----------------
template<int C>
__global__ void agg_kernel(const float* __restrict__ xin, float* __restrict__ out,
                           const int* __restrict__ perm, const int* __restrict__ mapping, int n)
{
    int warp = (blockIdx.x*blockDim.x + threadIdx.x) >> 5;
    int lane = threadIdx.x & 31;
    if (warp >= n) return;
    int old = perm ? perm[warp] : warp;
    int beg = g_rowptr[old], end = g_rowptr[old+1];
    if constexpr (C == 128){
        float4 acc = make_float4(0.f,0.f,0.f,0.f);
        for (int b = beg; b < end; b += 32){
            int e = b + lane;
            int s = -1;
            if (e < end){ s = g_esrc[e]; if (mapping) s = mapping[s]; }
            int cnt = min(32, end - b);
            for (int j = 0; j < cnt; j++){
                int sj = __shfl_sync(0xffffffffu, s, j);
                if (sj >= 0){
                    float4 v = ((const float4*)(xin + (size_t)sj*128))[lane];
                    acc.x += v.x; acc.y += v.y; acc.z += v.z; acc.w += v.w;
                }
            }
        }
        ((float4*)(out + (size_t)warp*128))[lane] = acc;
    } else {
        float2 acc = make_float2(0.f,0.f);
        for (int b = beg; b < end; b += 32){
            int e = b + lane;
            int s = -1;
            if (e < end){ s = g_esrc[e]; if (mapping) s = mapping[s]; }
            int cnt = min(32, end - b);
            for (int j = 0; j < cnt; j++){
                int sj = __shfl_sync(0xffffffffu, s, j);
                if (sj >= 0){
                    float2 v = ((const float2*)(xin + (size_t)sj*64))[lane];
                    acc.x += v.x; acc.y += v.y;
                }
            }
        }
        ((float2*)(out + (size_t)warp*64))[lane] = acc;
    }
}

// ---------------- tf32 split helpers ----------------
__device__ __forceinline__ void tf32_split(float a, float& hi, float& lo)
{
    unsigned h;
    asm("cvt.rna.tf32.f32 %0, %1;" : "=r"(h) : "f"(a));
    float hf = __uint_as_float(h);
    float l = a - hf;
    unsigned lu;
    asm("cvt.rna.tf32.f32 %0, %1;" : "=r"(lu) : "f"(l));
    hi = hf; lo = __uint_as_float(lu);
}

#define MMA_TF32(d, a0,a1,a2,a3, b0,b1) \
    asm volatile("mma.sync.aligned.m16n8k8.row.col.f32.tf32.tf32.f32 " \
        "{%0,%1,%2,%3}, {%4,%5,%6,%7}, {%8,%9}, {%0,%1,%2,%3};" \
        : "+f"((d)[0]), "+f"((d)[1]), "+f"((d)[2]), "+f"((d)[3]) \
        : "r"(a0), "r"(a1), "r"(a2), "r"(a3), "r"(b0), "r"(b1))

#define MMA_BF16(d, a0,a1,a2,a3, b0,b1) \
    asm volatile("mma.sync.aligned.m16n8k16.row.col.f32.bf16.bf16.f32 " \
        "{%0,%1,%2,%3}, {%4,%5,%6,%7}, {%8,%9}, {%0,%1,%2,%3};" \
        : "+f"((d)[0]), "+f"((d)[1]), "+f"((d)[2]), "+f"((d)[3]) \
        : "r"(a0), "r"(a1), "r"(a2), "r"(a3), "r"(b0), "r"(b1))

__device__ __forceinline__ unsigned short f2bf(float x)
{
    __nv_bfloat16 b = __float2bfloat16(x);
    return *reinterpret_cast<unsigned short*>(&b);
}
__device__ __forceinline__ void bf16_split(float x, unsigned short& hi, unsigned short& lo)
{
    __nv_bfloat16 h = __float2bfloat16(x);
    float hf = __bfloat162float(h);
    hi = *reinterpret_cast<unsigned short*>(&h);
    lo = f2bf(x - hf);
}

// ---------------- tf32 tensor-core GEMM (selection-critical layers) ----------------
template<int BN, int CIN, bool DUAL, bool RELU, bool GATHER>
__global__ void __launch_bounds__(256) gemm_tc_kernel(
    const float* __restrict__ A1, const float* __restrict__ A2,
    const float* __restrict__ W1, const float* __restrict__ W2,   // transposed [CIN][BN]
    const float* __restrict__ bias, const float* __restrict__ D,
    float* __restrict__ out, int n,
    const int* __restrict__ perm, const float* __restrict__ score)
{
    constexpr int BM = 128, BK = 16, TPB = 256;
    constexpr int BMp = 136, BNp = BN + 8;
    constexpr int AV = (BM*BK/4)/TPB;
    constexpr int BV = (BK*BN/4)/TPB;
    constexpr int TILES = CIN/BK;
    constexpr int T = (DUAL?2:1)*TILES;
    constexpr int MT = 2;
    constexpr int NT = BN/16;

    __shared__ float As[2][BK][BMp];
    __shared__ float Bs[2][BK][BNp];

    int tid = threadIdx.x, lane = tid & 31, warp = tid >> 5;
    int m0 = (warp >> 1) * 32;
    int n0 = (warp & 1) * (BN/2);
    int row0 = blockIdx.x * BM;
    int gid = lane >> 2, tig = lane & 3;

    int am[AV], akq[AV], aar[AV]; float asc[AV];
    #pragma unroll
    for (int u = 0; u < AV; u++){
        int f = tid + u*TPB;
        am[u] = f >> 2; akq[u] = (f & 3) << 2;
        int r = row0 + am[u];
        aar[u] = -1; asc[u] = 1.f;
        if (r < n){
            int ar = r;
            if (GATHER){ ar = perm[r]; asc[u] = score[ar]; }
            aar[u] = ar;
        }
    }
    int bkk[BV], bc4[BV];
    #pragma unroll
    for (int u = 0; u < BV; u++){
        int f = tid + u*TPB;
        bkk[u] = f / (BN/4); bc4[u] = (f % (BN/4)) << 2;
    }

    float4 ra[AV], rb[BV];
    auto load_tile = [&](int t){
        int ph = DUAL ? (t / TILES) : 0;
        int k0 = (t % TILES) * BK;
        const float* A = (DUAL && ph) ? A2 : A1;
        const float* W = (DUAL && ph) ? W2 : W1;
        #pragma unroll
        for (int u = 0; u < AV; u++){
            float4 v = make_float4(0.f,0.f,0.f,0.f);
            if (aar[u] >= 0){
                v = *(const float4*)(A + (size_t)aar[u]*CIN + k0 + akq[u]);
                if (GATHER){ v.x*=asc[u]; v.y*=asc[u]; v.z*=asc[u]; v.w*=asc[u]; }
            }
            ra[u] = v;
        }
        #pragma unroll
        for (int u = 0; u < BV; u++)
            rb[u] = *(const float4*)(W + (size_t)(k0 + bkk[u])*BN + bc4[u]);
    };
    auto store_split = [&](){
        #pragma unroll
        for (int u = 0; u < AV; u++){
            const float* s = (const float*)&ra[u];
            #pragma unroll
            for (int q = 0; q < 4; q++){
                float hi, lo; tf32_split(s[q], hi, lo);
                As[0][akq[u]+q][am[u]] = hi;
                As[1][akq[u]+q][am[u]] = lo;
            }
        }
        #pragma unroll
        for (int u = 0; u < BV; u++){
            const float* s = (const float*)&rb[u];
            #pragma unroll
            for (int q = 0; q < 4; q++){
                float hi, lo; tf32_split(s[q], hi, lo);
                Bs[0][bkk[u]][bc4[u]+q] = hi;
                Bs[1][bkk[u]][bc4[u]+q] = lo;
            }
        }
    };

    float acc[MT][NT][4];
    #pragma unroll
    for (int mi = 0; mi < MT; mi++)
        #pragma unroll
        for (int ni = 0; ni < NT; ni++)
            #pragma unroll
            for (int q = 0; q < 4; q++) acc[mi][ni][q] = 0.f;

    load_tile(0);
    for (int t = 0; t < T; t++){
        store_split();
        __syncthreads();
        if (t + 1 < T) load_tile(t + 1);
        #pragma unroll
        for (int kk = 0; kk < 2; kk++){
            int ko = kk * 8;
            unsigned ah[MT][4], al[MT][4];
            #pragma unroll
            for (int mi = 0; mi < MT; mi++){
                int mb = m0 + mi*16 + gid;
                ah[mi][0] = __float_as_uint(As[0][ko+tig  ][mb  ]);
                ah[mi][1] = __float_as_uint(As[0][ko+tig  ][mb+8]);
                ah[mi][2] = __float_as_uint(As[0][ko+tig+4][mb  ]);
                ah[mi][3] = __float_as_uint(As[0][ko+tig+4][mb+8]);
                al[mi][0] = __float_as_uint(As[1][ko+tig  ][mb  ]);
                al[mi][1] = __float_as_uint(As[1][ko+tig  ][mb+8]);
                al[mi][2] = __float_as_uint(As[1][ko+tig+4][mb  ]);
                al[mi][3] = __float_as_uint(As[1][ko+tig+4][mb+8]);
            }
            #pragma unroll
            for (int ni = 0; ni < NT; ni++){
                int nb = n0 + ni*8 + gid;
                unsigned bh0 = __float_as_uint(Bs[0][ko+tig  ][nb]);
                unsigned bh1 = __float_as_uint(Bs[0][ko+tig+4][nb]);
                unsigned bl0 = __float_as_uint(Bs[1][ko+tig  ][nb]);
                unsigned bl1 = __float_as_uint(Bs[1][ko+tig+4][nb]);
                #pragma unroll
                for (int mi = 0; mi < MT; mi++){
                    MMA_TF32(acc[mi][ni], ah[mi][0],ah[mi][1],ah[mi][2],ah[mi][3], bh0,bh1);
                    MMA_TF32(acc[mi][ni], ah[mi][0],ah[mi][1],ah[mi][2],ah[mi][3], bl0,bl1);
                    MMA_TF32(acc[mi][ni], al[mi][0],al[mi][1],al[mi][2],al[mi][3], bh0,bh1);
                }
            }
        }
        __syncthreads();
    }

    #pragma unroll
    for (int mi = 0; mi < MT; mi++){
        #pragma unroll
        for (int ni = 0; ni < NT; ni++){
            int cc = n0 + ni*8 + tig*2;
            #pragma unroll
            for (int h = 0; h < 2; h++){
                int rr = row0 + m0 + mi*16 + gid + h*8;
                if (rr < n){
                    float v0 = acc[mi][ni][h*2+0];
                    float v1 = acc[mi][ni][h*2+1];
                    if (bias){ v0 += __ldg(&bias[cc]); v1 += __ldg(&bias[cc+1]); }
                    if (D){ v0 += D[(size_t)rr*BN + cc]; v1 += D[(size_t)rr*BN + cc + 1]; }
                    if (RELU){ v0 = fmaxf(v0, 0.f); v1 = fmaxf(v1, 0.f); }
                    *(float2*)(out + (size_t)rr*BN + cc) = make_float2(v0, v1);
                }
            }
        }
    }
}

// ---------------- bf16-split tensor-core GEMM (selection-independent layers) ----------------
template<int BN, int CIN, bool DUAL, bool RELU, bool GATHER>
__global__ void __launch_bounds__(256) gemm_bf16_kernel(
    const float* __restrict__ A1, const float* __restrict__ A2,
    const float* __restrict__ W1, const float* __restrict__ W2,
    const float* __restrict__ bias, const float* __restrict__ D,
    float* __restrict__ out, int n,
    const int* __restrict__ perm, const float* __restrict__ score)
{
    constexpr int BM = 128, BK = 32, TPB = 256;
    constexpr int STR = 20;
    constexpr int AV = (BM*BK/4)/TPB;
    constexpr int BV = (BN*BK/4)/TPB;
    constexpr int TILES = CIN/BK;
    constexpr int T = (DUAL?2:1)*TILES;
    constexpr int MT = 2;
    constexpr int NT = BN/16;

    __shared__ unsigned As[2][BM][STR];
    __shared__ unsigned Bs[2][BN][STR];

    int tid = threadIdx.x, lane = tid & 31, warp = tid >> 5;
    int m0 = (warp >> 1) * 32;
    int n0 = (warp & 1) * (BN/2);
    int row0 = blockIdx.x * BM;
    int gid = lane >> 2, tig = lane & 3;

    int am[AV], akq[AV], aar[AV]; float asc[AV];
    #pragma unroll
    for (int u = 0; u < AV; u++){
        int f = tid + u*TPB;
        am[u] = f >> 3; akq[u] = (f & 7) << 2;
        int r = row0 + am[u];
        aar[u] = -1; asc[u] = 1.f;
        if (r < n){
            int ar = r;
            if (GATHER){ ar = perm[r]; asc[u] = score[ar]; }
            aar[u] = ar;
        }
    }
    int bm[BV], bkq[BV];
    #pragma unroll
    for (int u = 0; u < BV; u++){
        int f = tid + u*TPB;
        bm[u] = f >> 3; bkq[u] = (f & 7) << 2;
    }

    float4 ra[AV], rb[BV];
    auto load_tile = [&](int t){
        int ph = DUAL ? (t / TILES) : 0;
        int k0 = (t % TILES) * BK;
        const float* A = (DUAL && ph) ? A2 : A1;
        const float* W = (DUAL && ph) ? W2 : W1;
        #pragma unroll
        for (int u = 0; u < AV; u++){
            float4 v = make_float4(0.f,0.f,0.f,0.f);
            if (aar[u] >= 0){
                v = *(const float4*)(A + (size_t)aar[u]*CIN + k0 + akq[u]);
                if (GATHER){ v.x*=asc[u]; v.y*=asc[u]; v.z*=asc[u]; v.w*=asc[u]; }
            }
            ra[u] = v;
        }
        #pragma unroll
        for (int u = 0; u < BV; u++)
            rb[u] = *(const float4*)(W + (size_t)bm[u]*CIN + k0 + bkq[u]);
    };
    auto store_split = [&](){
        #pragma unroll
        for (int u = 0; u < AV; u++){
            const float* s = (const float*)&ra[u];
            unsigned short h0,l0,h1,l1,h2,l2,h3,l3;
            bf16_split(s[0],h0,l0); bf16_split(s[1],h1,l1);
            bf16_split(s[2],h2,l2); bf16_split(s[3],h3,l3);
            int w = akq[u] >> 1;
            As[0][am[u]][w  ] = (unsigned)h0 | ((unsigned)h1 << 16);
            As[0][am[u]][w+1] = (unsigned)h2 | ((unsigned)h3 << 16);
            As[1][am[u]][w  ] = (unsigned)l0 | ((unsigned)l1 << 16);
            As[1][am[u]][w+1] = (unsigned)l2 | ((unsigned)l3 << 16);
        }
        #pragma unroll
        for (int u = 0; u < BV; u++){
            const float* s = (const float*)&rb[u];
            unsigned short h0,l0,h1,l1,h2,l2,h3,l3;
            bf16_split(s[0],h0,l0); bf16_split(s[1],h1,l1);
            bf16_split(s[2],h2,l2); bf16_split(s[3],h3,l3);
            int w = bkq[u] >> 1;
            Bs[0][bm[u]][w  ] = (unsigned)h0 | ((unsigned)h1 << 16);
            Bs[0][bm[u]][w+1] = (unsigned)h2 | ((unsigned)h3 << 16);
            Bs[1][bm[u]][w  ] = (unsigned)l0 | ((unsigned)l1 << 16);
            Bs[1][bm[u]][w+1] = (unsigned)l2 | ((unsigned)l3 << 16);
        }
    };

    float acc[MT][NT][4];
    #pragma unroll
    for (int mi = 0; mi < MT; mi++)
        #pragma unroll
        for (int ni = 0; ni < NT; ni++)
            #pragma unroll
            for (int q = 0; q < 4; q++) acc[mi][ni][q] = 0.f;

    load_tile(0);
    for (int t = 0; t < T; t++){
        store_split();
        __syncthreads();
        if (t + 1 < T) load_tile(t + 1);
        #pragma unroll
        for (int kk = 0; kk < 2; kk++){
            int ko = kk * 8;
            unsigned ah[MT][4], al[MT][4];
            #pragma unroll
            for (int mi = 0; mi < MT; mi++){
                int mb = m0 + mi*16 + gid;
                ah[mi][0] = As[0][mb  ][ko+tig  ];
                ah[mi][1] = As[0][mb+8][ko+tig  ];
                ah[mi][2] = As[0][mb  ][ko+tig+4];
                ah[mi][3] = As[0][mb+8][ko+tig+4];
                al[mi][0] = As[1][mb  ][ko+tig  ];
                al[mi][1] = As[1][mb+8][ko+tig  ];
                al[mi][2] = As[1][mb  ][ko+tig+4];
                al[mi][3] = As[1][mb+8][ko+tig+4];
            }
            #pragma unroll
            for (int ni = 0; ni < NT; ni++){
                int nb = n0 + ni*8 + gid;
                unsigned bh0 = Bs[0][nb][ko+tig  ];
                unsigned bh1 = Bs[0][nb][ko+tig+4];
                unsigned bl0 = Bs[1][nb][ko+tig  ];
                unsigned bl1 = Bs[1][nb][ko+tig+4];
                #pragma unroll
                for (int mi = 0; mi < MT; mi++){
                    MMA_BF16(acc[mi][ni], ah[mi][0],ah[mi][1],ah[mi][2],ah[mi][3], bh0,bh1);
                    MMA_BF16(acc[mi][ni], ah[mi][0],ah[mi][1],ah[mi][2],ah[mi][3], bl0,bl1);
                    MMA_BF16(acc[mi][ni], al[mi][0],al[mi][1],al[mi][2],al[mi][3], bh0,bh1);
                }
            }
        }
        __syncthreads();
    }

    #pragma unroll
    for (int mi = 0; mi < MT; mi++){
        #pragma unroll
        for (int ni = 0; ni < NT; ni++){
            int cc = n0 + ni*8 + tig*2;
            #pragma unroll
            for (int h = 0; h < 2; h++){
                int rr = row0 + m0 + mi*16 + gid + h*8;
                if (rr < n){
                    float v0 = acc[mi][ni][h*2+0];
                    float v1 = acc[mi][ni][h*2+1];
                    if (bias){ v0 += __ldg(&bias[cc]); v1 += __ldg(&bias[cc+1]); }
                    if (D){ v0 += D[(size_t)rr*BN + cc]; v1 += D[(size_t)rr*BN + cc + 1]; }
                    if (RELU){ v0 = fmaxf(v0, 0.f); v1 = fmaxf(v1, 0.f); }
                    *(float2*)(out + (size_t)rr*BN + cc) = make_float2(v0, v1);
                }
            }
        }
    }
}

// ---------------- topk pooling ----------------
template<int C>
__global__ void score_kernel(const float* __restrict__ x, const float* __restrict__ w, int n)
{
    int gw = blockIdx.x*(blockDim.x>>5) + (threadIdx.x>>5);
    int lane = threadIdx.x & 31;
    if (gw >= n) return;
    float p, q;
    if constexpr (C == 128){
        float4 xv = ((const float4*)(x + (size_t)gw*128))[lane];
        float4 wv = ((const float4*)w)[lane];
        p = xv.x*wv.x + xv.y*wv.y + xv.z*wv.z + xv.w*wv.w;
        q = wv.x*wv.x + wv.y*wv.y + wv.z*wv.z + wv.w*wv.w;
    } else {
        float2 xv = ((const float2*)(x + (size_t)gw*64))[lane];
        float2 wv = ((const float2*)w)[lane];
        p = xv.x*wv.x + xv.y*wv.y;
        q = wv.x*wv.x + wv.y*wv.y;
    }
    #pragma unroll
    for (int off = 16; off; off >>= 1){
        p += __shfl_xor_sync(0xffffffffu, p, off);
        q += __shfl_xor_sync(0xffffffffu, q, off);
    }
    if (lane == 0){
        float s = tanhf(p / sqrtf(q));
        g_score[gw] = s;
        unsigned u = __float_as_uint(s);
        u = (u & 0x80000000u) ? ~u : (u | 0x80000000u);
        g_key[gw] = u;
    }
}

// ONE-KERNEL radix select + compact (single block, 1024 threads).
// 4 byte-passes to find the k-th largest key, then count strictly-greater,
// then compact with lowest-index tie-break (matches jax.lax.top_k ordering set).
__global__ void __launch_bounds__(1024) topk_select_kernel(
    int* __restrict__ mapping, int* __restrict__ perm, int n, int k)
{
    __shared__ unsigned hist[256];
    __shared__ int ws[32];
    __shared__ int s_b, s_rem;

    unsigned prefix = 0;
    int remaining = k;
    for (int pass = 3; pass >= 0; pass--){
        for (int t = threadIdx.x; t < 256; t += 1024) hist[t] = 0;
        __syncthreads();
        int shf = (pass+1)*8;
        unsigned pref_hi = (pass == 3) ? 0u : (prefix >> shf);
        for (int base = 0; base < n; base += 1024){
            int i = base + threadIdx.x;
            if (i < n){
                unsigned key = g_key[i];
                bool ok = (pass == 3) || ((key >> shf) == pref_hi);
                if (ok) atomicAdd(&hist[(key >> (pass*8)) & 255], 1u);
            }
        }
        __syncthreads();
        if (threadIdx.x == 0){
            unsigned r = (unsigned)remaining;
            unsigned c = 0; int b = 255;
            for (; b > 0; b--){
                unsigned h = hist[b];
                if (c + h >= r) break;
                c += h;
            }
            s_b = b; s_rem = (int)(r - c);
        }
        __syncthreads();
        prefix |= ((unsigned)s_b) << (pass*8);
        remaining = s_rem;
        __syncthreads();
    }

    // count strictly-greater
    unsigned thr = prefix;
    int local = 0;
    for (int base = 0; base < n; base += 1024){
        int i = base + threadIdx.x;
        if (i < n) local += (g_key[i] > thr) ? 1 : 0;
    }
    int totG; block_scan_incl(local, totG, ws);
    int need_eq = k - totG;

    // compact
    int run_eq = 0, run_sel = 0;
    for (int base = 0; base < n; base += 1024){
        int i = base + threadIdx.x;
        int gt = 0, eq = 0;
        if (i < n){
            unsigned kv = g_key[i];
            gt = (kv > thr); eq = (kv == thr);
        }
        int tot_eq; int incl_eq = block_scan_incl(eq, tot_eq, ws);
        int excl_eq = incl_eq - eq;
        int sel = gt | (eq & ((run_eq + excl_eq) < need_eq ? 1 : 0));
        int tot_sel; int incl_sel = block_scan_incl(sel, tot_sel, ws);
        if (i < n){
            if (sel){
                int idx = run_sel + incl_sel - 1;
                mapping[i] = idx;
                perm[idx] = i;
            } else mapping[i] = -1;
        }
        run_eq += tot_eq; run_sel += tot_sel;
    }
}

// fused compose of level0->level2 mapping and perm
__global__ void compose_kernel()
{
    int i = blockIdx.x*blockDim.x + threadIdx.x;
    if (i < N0){ int m = g_map1[i]; g_map02[i] = (m >= 0) ? g_map2[m] : -1; }
    if (i < K2) g_perm02[i] = g_perm1[g_perm2[i]];
}

template<int C>
__global__ void unpool_kernel(const float* __restrict__ xb, const float* __restrict__ xs,
                              const int* __restrict__ mapping, float* __restrict__ out, int n)
{
    int idx = blockIdx.x*blockDim.x + threadIdx.x;
    int total = n * (C/4);
    if (idx >= total) return;
    int i = idx / (C/4), t = idx % (C/4);
    int m = mapping[i];
    float4 v = ((const float4*)(xb + (size_t)i*C))[t];
    if (m >= 0){
        float4 w = ((const float4*)(xs + (size_t)m*C))[t];
        v.x += w.x; v.y += w.y; v.z += w.z; v.w += w.w;
    }
    ((float4*)(out + (size_t)i*C))[t] = v;
}

// ---------------- final linear + log_softmax (warp per node) ----------------
__global__ void final_kernel(const float* __restrict__ x, const float* __restrict__ lw,
                             const float* __restrict__ lb, float* __restrict__ out, int n)
{
    int gw = blockIdx.x*(blockDim.x>>5) + (threadIdx.x>>5);
    int lane = threadIdx.x & 31;
    if (gw >= n) return;
    float4 xv = ((const float4*)(x + (size_t)gw*128))[lane];
    float lg[10]; float myv = 0.f;
    #pragma unroll
    for (int c = 0; c < 10; c++){
        float4 wv = ((const float4*)(lw + c*128))[lane];
        float p = xv.x*wv.x + xv.y*wv.y + xv.z*wv.z + xv.w*wv.w;
        #pragma unroll
        for (int off = 16; off; off >>= 1) p += __shfl_xor_sync(0xffffffffu, p, off);
        p += __ldg(&lb[c]);
        lg[c] = p;
        if (lane == c) myv = p;
    }
    float m = lg[0];
    #pragma unroll
    for (int c = 1; c < 10; c++) m = fmaxf(m, lg[c]);
    float s = 0.f;
    #pragma unroll
    for (int c = 0; c < 10; c++) s += expf(lg[c] - m);
    float lse = m + logf(s);
    if (lane < 10) out[(size_t)gw*10 + lane] = myv - lse;
}

// ---------------- host driver ----------------
extern "C" void kernel_launch(void* const* d_in, const int* in_sizes, int n_in,
                              void* d_out, int out_size)
{
    (void)in_sizes; (void)n_in; (void)out_size;
    const float* x    = (const float*)d_in[0];
    const int*   ei   = (const int*)d_in[1];
    const int*   src0 = ei;
    const int*   dst0 = ei + E0;
    const float *w1r=(const float*)d_in[2], *w1o=(const float*)d_in[3], *b1=(const float*)d_in[4], *p1w=(const float*)d_in[5];
    const float *w2r=(const float*)d_in[6], *w2o=(const float*)d_in[7], *b2=(const float*)d_in[8], *p2w=(const float*)d_in[9];
    const float *w3r=(const float*)d_in[10],*w3o=(const float*)d_in[11],*b3=(const float*)d_in[12];
    const float *w4r=(const float*)d_in[13],*w4o=(const float*)d_in[14],*b4=(const float*)d_in[15];
    const float *w5r=(const float*)d_in[16],*w5o=(const float*)d_in[17],*b5=(const float*)d_in[18];
    const float *lw =(const float*)d_in[19],*lb =(const float*)d_in[20];
    float* out = (float*)d_out;

    float *x1,*agg,*tbuf,*x2,*x3,*u1,*x4,*u2,*x5,*wT,*score;
    int *rowptr,*fill,*part,*partx,*map1,*perm1,*map2,*perm2,*map02,*perm02;
    cudaGetSymbolAddress((void**)&x1, g_x1);
    cudaGetSymbolAddress((void**)&agg, g_agg);
    cudaGetSymbolAddress((void**)&tbuf, g_t);
    cudaGetSymbolAddress((void**)&x2, g_x2);
    cudaGetSymbolAddress((void**)&x3, g_x3);
    cudaGetSymbolAddress((void**)&u1, g_u1);
    cudaGetSymbolAddress((void**)&x4, g_x4);
    cudaGetSymbolAddress((void**)&u2, g_u2);
    cudaGetSymbolAddress((void**)&x5, g_x5);
    cudaGetSymbolAddress((void**)&wT, g_wT);
    cudaGetSymbolAddress((void**)&score, g_score);
    cudaGetSymbolAddress((void**)&rowptr, g_rowptr);
    cudaGetSymbolAddress((void**)&fill, g_fill);
    cudaGetSymbolAddress((void**)&part, g_part);
    cudaGetSymbolAddress((void**)&partx, g_partx);
    cudaGetSymbolAddress((void**)&map1, g_map1);
    cudaGetSymbolAddress((void**)&perm1, g_perm1);
    cudaGetSymbolAddress((void**)&map2, g_map2);
    cudaGetSymbolAddress((void**)&perm2, g_perm2);
    cudaGetSymbolAddress((void**)&map02, g_map02);
    cudaGetSymbolAddress((void**)&perm02, g_perm02);

    const int W = 16384;

    cudaStream_t s2;
    cudaEvent_t ev1, ev2;
    cudaStreamCreateWithFlags(&s2, cudaStreamNonBlocking);
    cudaEventCreateWithFlags(&ev1, cudaEventDisableTiming);
    cudaEventCreateWithFlags(&ev2, cudaEventDisableTiming);

    // fork s2 from main
    cudaEventRecord(ev1, 0);
    cudaStreamWaitEvent(s2, ev1, 0);

    // launch order: 1..3 small, 4 = tf32 GEMM (profiled)
    {
        dim3 g(64, 4);
        transpose_all_kernel<<<g,256>>>(w1r,w1o,w2r,w2o, wT);                    // 1 (main)
    }
    zero_int_kernel<<<(N0+255)/256,256,0,s2>>>(fill, N0);                        // 2 (s2)
    edge_count_kernel<<<(E0+255)/256,256,0,s2>>>(dst0);                          // 3 (s2)
    gemm_tc_kernel<128,128,false,false,false><<<(N0+127)/128,256>>>(             // 4 (main, profiled)
        x, nullptr, wT+1*W, nullptr, nullptr, nullptr, x1, N0, nullptr, nullptr);
    deg_reduce_kernel<<<NB_SCAN,1024,0,s2>>>(fill, part, N0);                    // 5 (s2)
    scan_kernel<<<1,1024,0,s2>>>(part, partx, NB_SCAN);                          // 6 (s2)
    deg_apply_kernel<<<NB_SCAN,1024,0,s2>>>(fill, partx, rowptr, N0);            // 7 (s2)
    edge_scatter_kernel<<<(E0+255)/256,256,0,s2>>>(src0, dst0);                  // 8 (s2)
    agg_kernel<128><<<(N0+7)/8,256,0,s2>>>(x, agg, nullptr, nullptr, N0);        // 9 (s2)
    cudaEventRecord(ev2, s2);
    cudaStreamWaitEvent(0, ev2, 0);

    // conv1 rel-half (in-place D add + bias + relu)
    gemm_tc_kernel<128,128,false,true,false><<<(N0+127)/128,256>>>(
        agg, nullptr, wT+0*W, nullptr, b1, x1, x1, N0, nullptr, nullptr);

    // pool1: score + single-kernel select
    score_kernel<128><<<(N0+7)/8,256>>>(x1, p1w, N0);
    topk_select_kernel<<<1,1024>>>(map1, perm1, N0, K1);

    // conv2: 128 -> 64 on level 1 (tf32; feeds pool2 scores)
    gemm_tc_kernel<64,128,false,false,true><<<(K1+127)/128,256>>>(
        x1, nullptr, wT+2*W, nullptr, nullptr, nullptr, tbuf, K1, perm1, score);
    agg_kernel<64><<<(K1+7)/8,256>>>(tbuf, agg, perm1, map1, K1);
    gemm_tc_kernel<64,128,false,true,true><<<(K1+127)/128,256>>>(
        x1, nullptr, wT+3*W, nullptr, b2, agg, x2, K1, perm1, score);

    // pool2
    score_kernel<64><<<(K1+7)/8,256>>>(x2, p2w, K1);
    topk_select_kernel<<<1,1024>>>(map2, perm2, K1, K2);

    // composed mappings level0 -> level2
    compose_kernel<<<(N0+255)/256,256>>>();

    // conv3: 64 -> 64 on level 2 (bf16-split)
    gemm_bf16_kernel<64,64,false,false,true><<<(K2+127)/128,256>>>(
        x2, nullptr, w3r, nullptr, nullptr, nullptr, tbuf, K2, perm2, score);
    agg_kernel<64><<<(K2+7)/8,256>>>(tbuf, agg, perm02, map02, K2);
    gemm_bf16_kernel<64,64,false,true,true><<<(K2+127)/128,256>>>(
        x2, nullptr, w3o, nullptr, b3, agg, x3, K2, perm2, score);

    // unpool1 + skip
    unpool_kernel<64><<<(K1*16+255)/256,256>>>(x2, x3, map2, u1, K1);

    // conv4: 64 -> 128 on level 1 (bf16-split)
    agg_kernel<64><<<(K1+7)/8,256>>>(u1, agg, perm1, map1, K1);
    gemm_bf16_kernel<128,64,true,true,false><<<(K1+127)/128,256>>>(
        agg, u1, w4r, w4o, b4, nullptr, x4, K1, nullptr, nullptr);

    // unpool2 + skip
    unpool_kernel<128><<<(N0*32+255)/256,256>>>(x1, x4, map1, u2, N0);

    // conv5: 128 -> 128 on level 0 (bf16-split)
    agg_kernel<128><<<(N0+7)/8,256>>>(u2, agg, nullptr, nullptr, N0);
    gemm_bf16_kernel<128,128,true,true,false><<<(N0+127)/128,256>>>(
        agg, u2, w5r, w5o, b5, nullptr, x5, N0, nullptr, nullptr);

    // final linear + log_softmax
    final_kernel<<<(N0+7)/8,256>>>(x5, lw, lb, out, N0);
}

// round 8
// speedup vs baseline: 1.1657x; 1.0362x over previous
#include <cuda_runtime.h>
#include <cuda_bf16.h>
#include <math.h>

#define N0 50000
#define E0 1600000
#define K1 40000
#define K2 32000
#define NB_SCAN 49   // ceil(N0/1024)

// ---------------- scratch (device globals; no runtime allocation) ----------------
__device__ float g_x1[N0*128];
__device__ float g_agg[N0*128];
__device__ float g_t[K1*64];
__device__ float g_x2[K1*64];
__device__ float g_x3[K2*64];
__device__ float g_u1[K1*64];
__device__ float g_x4[K1*128];
__device__ float g_u2[N0*128];
__device__ float g_x5[N0*128];
__device__ int   g_rowptr[N0+1];
__device__ int   g_fill[N0];
__device__ int   g_part[64];
__device__ int   g_partx[66];
__device__ int   g_esrc[E0];
__device__ float g_score[N0];
__device__ unsigned g_key[N0];
__device__ int   g_map1[N0];
__device__ int   g_perm1[K1];
__device__ int   g_map2[K1];
__device__ int   g_perm2[K2];
__device__ int   g_map02[N0];
__device__ int   g_perm02[K2];
__device__ float g_wT[4*128*128];

// ---------------- CSR build ----------------
__global__ void zero_int_kernel(int* p, int n)
{
    int i = blockIdx.x*blockDim.x + threadIdx.x;
    if (i < n) p[i] = 0;
}

__global__ void edge_count_kernel(const int* __restrict__ dst)
{
    int e = blockIdx.x*blockDim.x + threadIdx.x;
    if (e < E0) atomicAdd(&g_fill[dst[e]], 1);
}

__device__ __forceinline__ int block_scan_incl(int val, int& total, int* ws)
{
    int lane = threadIdx.x & 31, wid = threadIdx.x >> 5;
    int x = val;
    #pragma unroll
    for (int off = 1; off < 32; off <<= 1){
        int y = __shfl_up_sync(0xffffffffu, x, off);
        if (lane >= off) x += y;
    }
    if (lane == 31) ws[wid] = x;
    __syncthreads();
    if (wid == 0){
        int s = ws[lane];
        #pragma unroll
        for (int off = 1; off < 32; off <<= 1){
            int y = __shfl_up_sync(0xffffffffu, s, off);
            if (lane >= off) s += y;
        }
        ws[lane] = s;
    }
    __syncthreads();
    int res = x + (wid ? ws[wid-1] : 0);
    total = ws[31];
    __syncthreads();
    return res;
}

__global__ void scan_kernel(const int* __restrict__ in, int* __restrict__ out, int n)
{
    __shared__ int ws[32];
    int run = 0;
    for (int base = 0; base < n; base += 1024){
        int i = base + threadIdx.x;
        int v = (i < n) ? in[i] : 0;
        int tot; int incl = block_scan_incl(v, tot, ws);
        if (i < n) out[i] = run + incl - v;
        run += tot;
    }
    if (threadIdx.x == 0) out[n] = run;
}

__global__ void deg_reduce_kernel(const int* __restrict__ in, int* __restrict__ part, int n)
{
    __shared__ int ws[32];
    int i = blockIdx.x*1024 + threadIdx.x;
    int v = (i < n) ? in[i] : 0;
    int lane = threadIdx.x & 31, wid = threadIdx.x >> 5;
    #pragma unroll
    for (int off = 16; off; off >>= 1) v += __shfl_down_sync(0xffffffffu, v, off);
    if (lane == 0) ws[wid] = v;
    __syncthreads();
    if (wid == 0){
        v = ws[lane];
        #pragma unroll
        for (int off = 16; off; off >>= 1) v += __shfl_down_sync(0xffffffffu, v, off);
        if (lane == 0) part[blockIdx.x] = v;
    }
}

__global__ void deg_apply_kernel(const int* __restrict__ in, const int* __restrict__ partx,
                                 int* __restrict__ rowptr, int n)
{
    __shared__ int ws[32];
    int i = blockIdx.x*1024 + threadIdx.x;
    int v = (i < n) ? in[i] : 0;
    int tot; int incl = block_scan_incl(v, tot, ws);
    if (i < n) rowptr[i] = partx[blockIdx.x] + incl - v;
    if (i == n) rowptr[n] = partx[gridDim.x];
}

__global__ void edge_scatter_kernel(const int* __restrict__ src, const int* __restrict__ dst)
{
    int e = blockIdx.x*blockDim.x + threadIdx.x;
    if (e < E0){
        int d = dst[e];
        int off = atomicSub(&g_fill[d], 1) - 1;
        g_esrc[g_rowptr[d] + off] = src[e];
    }
}

// ---------------- transpose of the 4 tf32-path weight matrices ----------------
__global__ void transpose_all_kernel(
    const float* w0, const float* w1, const float* w2, const float* w3,
    float* __restrict__ wT)
{
    const float* ws[4] = {w0,w1,w2,w3};
    const int CO[4] = {128,128,64,64};
    const int CI[4] = {128,128,128,128};
    int m = blockIdx.y;
    int idx = blockIdx.x*blockDim.x + threadIdx.x;
    int nEl = CO[m]*CI[m];
    if (idx < nEl){
        int r = idx / CI[m], c = idx % CI[m];
        wT[m*16384 + c*CO[m] + r] = ws[m][idx];
    }
}

// ---------------- aggregation: warp per node, vectorized row gather ----------------
template<int C>
__global__ void agg_kernel(const float* __restrict__ xin, float* __restrict__ out,
                           const int* __restrict__ perm, const int* __restrict__ mapping, int n)
{
    int warp = (blockIdx.x*blockDim.x + threadIdx.x) >> 5;
    int lane = threadIdx.x & 31;
    if (warp >= n) return;
    int old = perm ? perm[warp] : warp;
    int beg = g_rowptr[old], end = g_rowptr[old+1];
    if constexpr (C == 128){
        float4 acc = make_float4(0.f,0.f,0.f,0.f);
        for (int b = beg; b < end; b += 32){
            int e = b + lane;
            int s = -1;
            if (e < end){ s = g_esrc[e]; if (mapping) s = mapping[s]; }
            int cnt = min(32, end - b);
            for (int j = 0; j < cnt; j++){
                int sj = __shfl_sync(0xffffffffu, s, j);
                if (sj >= 0){
                    float4 v = ((const float4*)(xin + (size_t)sj*128))[lane];
                    acc.x += v.x; acc.y += v.y; acc.z += v.z; acc.w += v.w;
                }
            }
        }
        ((float4*)(out + (size_t)warp*128))[lane] = acc;
    } else {
        float2 acc = make_float2(0.f,0.f);
        for (int b = beg; b < end; b += 32){
            int e = b + lane;
            int s = -1;
            if (e < end){ s = g_esrc[e]; if (mapping) s = mapping[s]; }
            int cnt = min(32, end - b);
            for (int j = 0; j < cnt; j++){
                int sj = __shfl_sync(0xffffffffu, s, j);
                if (sj >= 0){
                    float2 v = ((const float2*)(xin + (size_t)sj*64))[lane];
                    acc.x += v.x; acc.y += v.y;
                }
            }
        }
        ((float2*)(out + (size_t)warp*64))[lane] = acc;
    }
}

// ---------------- tf32 split helpers ----------------
__device__ __forceinline__ void tf32_split(float a, float& hi, float& lo)
{
    unsigned h;
    asm("cvt.rna.tf32.f32 %0, %1;" : "=r"(h) : "f"(a));
    float hf = __uint_as_float(h);
    float l = a - hf;
    unsigned lu;
    asm("cvt.rna.tf32.f32 %0, %1;" : "=r"(lu) : "f"(l));
    hi = hf; lo = __uint_as_float(lu);
}

#define MMA_TF32(d, a0,a1,a2,a3, b0,b1) \
    asm volatile("mma.sync.aligned.m16n8k8.row.col.f32.tf32.tf32.f32 " \
        "{%0,%1,%2,%3}, {%4,%5,%6,%7}, {%8,%9}, {%0,%1,%2,%3};" \
        : "+f"((d)[0]), "+f"((d)[1]), "+f"((d)[2]), "+f"((d)[3]) \
        : "r"(a0), "r"(a1), "r"(a2), "r"(a3), "r"(b0), "r"(b1))

#define MMA_BF16(d, a0,a1,a2,a3, b0,b1) \
    asm volatile("mma.sync.aligned.m16n8k16.row.col.f32.bf16.bf16.f32 " \
        "{%0,%1,%2,%3}, {%4,%5,%6,%7}, {%8,%9}, {%0,%1,%2,%3};" \
        : "+f"((d)[0]), "+f"((d)[1]), "+f"((d)[2]), "+f"((d)[3]) \
        : "r"(a0), "r"(a1), "r"(a2), "r"(a3), "r"(b0), "r"(b1))

__device__ __forceinline__ unsigned short f2bf(float x)
{
    __nv_bfloat16 b = __float2bfloat16(x);
    return *reinterpret_cast<unsigned short*>(&b);
}
__device__ __forceinline__ void bf16_split(float x, unsigned short& hi, unsigned short& lo)
{
    __nv_bfloat16 h = __float2bfloat16(x);
    float hf = __bfloat162float(h);
    hi = *reinterpret_cast<unsigned short*>(&h);
    lo = f2bf(x - hf);
}

// ---------------- tf32 tensor-core GEMM (selection-critical layers) ----------------
// __launch_bounds__(256,2): force 2 CTAs/SM (regs<=128) — latency hiding across CTAs.
template<int BN, int CIN, bool DUAL, bool RELU, bool GATHER>
__global__ void __launch_bounds__(256, 2) gemm_tc_kernel(
    const float* __restrict__ A1, const float* __restrict__ A2,
    const float* __restrict__ W1, const float* __restrict__ W2,   // transposed [CIN][BN]
    const float* __restrict__ bias, const float* __restrict__ D,
    float* __restrict__ out, int n,
    const int* __restrict__ perm, const float* __restrict__ score)
{
    constexpr int BM = 128, BK = 16, TPB = 256;
    constexpr int BMp = 136, BNp = BN + 8;
    constexpr int AV = (BM*BK/4)/TPB;
    constexpr int BV = (BK*BN/4)/TPB;
    constexpr int TILES = CIN/BK;
    constexpr int T = (DUAL?2:1)*TILES;
    constexpr int MT = 2;
    constexpr int NT = BN/16;

    __shared__ float As[2][BK][BMp];
    __shared__ float Bs[2][BK][BNp];

    int tid = threadIdx.x, lane = tid & 31, warp = tid >> 5;
    int m0 = (warp >> 1) * 32;
    int n0 = (warp & 1) * (BN/2);
    int row0 = blockIdx.x * BM;
    int gid = lane >> 2, tig = lane & 3;

    int am[AV], akq[AV], aar[AV]; float asc[AV];
    #pragma unroll
    for (int u = 0; u < AV; u++){
        int f = tid + u*TPB;
        am[u] = f >> 2; akq[u] = (f & 3) << 2;
        int r = row0 + am[u];
        aar[u] = -1; asc[u] = 1.f;
        if (r < n){
            int ar = r;
            if (GATHER){ ar = perm[r]; asc[u] = score[ar]; }
            aar[u] = ar;
        }
    }
    int bkk[BV], bc4[BV];
    #pragma unroll
    for (int u = 0; u < BV; u++){
        int f = tid + u*TPB;
        bkk[u] = f / (BN/4); bc4[u] = (f % (BN/4)) << 2;
    }

    float4 ra[AV], rb[BV];
    auto load_tile = [&](int t){
        int ph = DUAL ? (t / TILES) : 0;
        int k0 = (t % TILES) * BK;
        const float* A = (DUAL && ph) ? A2 : A1;
        const float* W = (DUAL && ph) ? W2 : W1;
        #pragma unroll
        for (int u = 0; u < AV; u++){
            float4 v = make_float4(0.f,0.f,0.f,0.f);
            if (aar[u] >= 0){
                v = *(const float4*)(A + (size_t)aar[u]*CIN + k0 + akq[u]);
                if (GATHER){ v.x*=asc[u]; v.y*=asc[u]; v.z*=asc[u]; v.w*=asc[u]; }
            }
            ra[u] = v;
        }
        #pragma unroll
        for (int u = 0; u < BV; u++)
            rb[u] = *(const float4*)(W + (size_t)(k0 + bkk[u])*BN + bc4[u]);
    };
    auto store_split = [&](){
        #pragma unroll
        for (int u = 0; u < AV; u++){
            const float* s = (const float*)&ra[u];
            #pragma unroll
            for (int q = 0; q < 4; q++){
                float hi, lo; tf32_split(s[q], hi, lo);
                As[0][akq[u]+q][am[u]] = hi;
                As[1][akq[u]+q][am[u]] = lo;
            }
        }
        #pragma unroll
        for (int u = 0; u < BV; u++){
            const float* s = (const float*)&rb[u];
            #pragma unroll
            for (int q = 0; q < 4; q++){
                float hi, lo; tf32_split(s[q], hi, lo);
                Bs[0][bkk[u]][bc4[u]+q] = hi;
                Bs[1][bkk[u]][bc4[u]+q] = lo;
            }
        }
    };

    float acc[MT][NT][4];
    #pragma unroll
    for (int mi = 0; mi < MT; mi++)
        #pragma unroll
        for (int ni = 0; ni < NT; ni++)
            #pragma unroll
            for (int q = 0; q < 4; q++) acc[mi][ni][q] = 0.f;

    load_tile(0);
    for (int t = 0; t < T; t++){
        store_split();
        __syncthreads();
        if (t + 1 < T) load_tile(t + 1);
        #pragma unroll
        for (int kk = 0; kk < 2; kk++){
            int ko = kk * 8;
            unsigned ah[MT][4], al[MT][4];
            #pragma unroll
            for (int mi = 0; mi < MT; mi++){
                int mb = m0 + mi*16 + gid;
                ah[mi][0] = __float_as_uint(As[0][ko+tig  ][mb  ]);
                ah[mi][1] = __float_as_uint(As[0][ko+tig  ][mb+8]);
                ah[mi][2] = __float_as_uint(As[0][ko+tig+4][mb  ]);
                ah[mi][3] = __float_as_uint(As[0][ko+tig+4][mb+8]);
                al[mi][0] = __float_as_uint(As[1][ko+tig  ][mb  ]);
                al[mi][1] = __float_as_uint(As[1][ko+tig  ][mb+8]);
                al[mi][2] = __float_as_uint(As[1][ko+tig+4][mb  ]);
                al[mi][3] = __float_as_uint(As[1][ko+tig+4][mb+8]);
            }
            #pragma unroll
            for (int ni = 0; ni < NT; ni++){
                int nb = n0 + ni*8 + gid;
                unsigned bh0 = __float_as_uint(Bs[0][ko+tig  ][nb]);
                unsigned bh1 = __float_as_uint(Bs[0][ko+tig+4][nb]);
                unsigned bl0 = __float_as_uint(Bs[1][ko+tig  ][nb]);
                unsigned bl1 = __float_as_uint(Bs[1][ko+tig+4][nb]);
                #pragma unroll
                for (int mi = 0; mi < MT; mi++){
                    MMA_TF32(acc[mi][ni], ah[mi][0],ah[mi][1],ah[mi][2],ah[mi][3], bh0,bh1);
                    MMA_TF32(acc[mi][ni], ah[mi][0],ah[mi][1],ah[mi][2],ah[mi][3], bl0,bl1);
                    MMA_TF32(acc[mi][ni], al[mi][0],al[mi][1],al[mi][2],al[mi][3], bh0,bh1);
                }
            }
        }
        __syncthreads();
    }

    #pragma unroll
    for (int mi = 0; mi < MT; mi++){
        #pragma unroll
        for (int ni = 0; ni < NT; ni++){
            int cc = n0 + ni*8 + tig*2;
            #pragma unroll
            for (int h = 0; h < 2; h++){
                int rr = row0 + m0 + mi*16 + gid + h*8;
                if (rr < n){
                    float v0 = acc[mi][ni][h*2+0];
                    float v1 = acc[mi][ni][h*2+1];
                    if (bias){ v0 += __ldg(&bias[cc]); v1 += __ldg(&bias[cc+1]); }
                    if (D){ v0 += D[(size_t)rr*BN + cc]; v1 += D[(size_t)rr*BN + cc + 1]; }
                    if (RELU){ v0 = fmaxf(v0, 0.f); v1 = fmaxf(v1, 0.f); }
                    *(float2*)(out + (size_t)rr*BN + cc) = make_float2(v0, v1);
                }
            }
        }
    }
}

// ---------------- bf16-split tensor-core GEMM (selection-independent layers) ----------------
template<int BN, int CIN, bool DUAL, bool RELU, bool GATHER>
__global__ void __launch_bounds__(256, 2) gemm_bf16_kernel(
    const float* __restrict__ A1, const float* __restrict__ A2,
    const float* __restrict__ W1, const float* __restrict__ W2,
    const float* __restrict__ bias, const float* __restrict__ D,
    float* __restrict__ out, int n,
    const int* __restrict__ perm, const float* __restrict__ score)
{
    constexpr int BM = 128, BK = 32, TPB = 256;
    constexpr int STR = 20;
    constexpr int AV = (BM*BK/4)/TPB;
    constexpr int BV = (BN*BK/4)/TPB;
    constexpr int TILES = CIN/BK;
    constexpr int T = (DUAL?2:1)*TILES;
    constexpr int MT = 2;
    constexpr int NT = BN/16;

    __shared__ unsigned As[2][BM][STR];
    __shared__ unsigned Bs[2][BN][STR];

    int tid = threadIdx.x, lane = tid & 31, warp = tid >> 5;
    int m0 = (warp >> 1) * 32;
    int n0 = (warp & 1) * (BN/2);
    int row0 = blockIdx.x * BM;
    int gid = lane >> 2, tig = lane & 3;

    int am[AV], akq[AV], aar[AV]; float asc[AV];
    #pragma unroll
    for (int u = 0; u < AV; u++){
        int f = tid + u*TPB;
        am[u] = f >> 3; akq[u] = (f & 7) << 2;
        int r = row0 + am[u];
        aar[u] = -1; asc[u] = 1.f;
        if (r < n){
            int ar = r;
            if (GATHER){ ar = perm[r]; asc[u] = score[ar]; }
            aar[u] = ar;
        }
    }
    int bm[BV], bkq[BV];
    #pragma unroll
    for (int u = 0; u < BV; u++){
        int f = tid + u*TPB;
        bm[u] = f >> 3; bkq[u] = (f & 7) << 2;
    }

    float4 ra[AV], rb[BV];
    auto load_tile = [&](int t){
        int ph = DUAL ? (t / TILES) : 0;
        int k0 = (t % TILES) * BK;
        const float* A = (DUAL && ph) ? A2 : A1;
        const float* W = (DUAL && ph) ? W2 : W1;
        #pragma unroll
        for (int u = 0; u < AV; u++){
            float4 v = make_float4(0.f,0.f,0.f,0.f);
            if (aar[u] >= 0){
                v = *(const float4*)(A + (size_t)aar[u]*CIN + k0 + akq[u]);
                if (GATHER){ v.x*=asc[u]; v.y*=asc[u]; v.z*=asc[u]; v.w*=asc[u]; }
            }
            ra[u] = v;
        }
        #pragma unroll
        for (int u = 0; u < BV; u++)
            rb[u] = *(const float4*)(W + (size_t)bm[u]*CIN + k0 + bkq[u]);
    };
    auto store_split = [&](){
        #pragma unroll
        for (int u = 0; u < AV; u++){
            const float* s = (const float*)&ra[u];
            unsigned short h0,l0,h1,l1,h2,l2,h3,l3;
            bf16_split(s[0],h0,l0); bf16_split(s[1],h1,l1);
            bf16_split(s[2],h2,l2); bf16_split(s[3],h3,l3);
            int w = akq[u] >> 1;
            As[0][am[u]][w  ] = (unsigned)h0 | ((unsigned)h1 << 16);
            As[0][am[u]][w+1] = (unsigned)h2 | ((unsigned)h3 << 16);
            As[1][am[u]][w  ] = (unsigned)l0 | ((unsigned)l1 << 16);
            As[1][am[u]][w+1] = (unsigned)l2 | ((unsigned)l3 << 16);
        }
        #pragma unroll
        for (int u = 0; u < BV; u++){
            const float* s = (const float*)&rb[u];
            unsigned short h0,l0,h1,l1,h2,l2,h3,l3;
            bf16_split(s[0],h0,l0); bf16_split(s[1],h1,l1);
            bf16_split(s[2],h2,l2); bf16_split(s[3],h3,l3);
            int w = bkq[u] >> 1;
            Bs[0][bm[u]][w  ] = (unsigned)h0 | ((unsigned)h1 << 16);
            Bs[0][bm[u]][w+1] = (unsigned)h2 | ((unsigned)h3 << 16);
            Bs[1][bm[u]][w  ] = (unsigned)l0 | ((unsigned)l1 << 16);
            Bs[1][bm[u]][w+1] = (unsigned)l2 | ((unsigned)l3 << 16);
        }
    };

    float acc[MT][NT][4];
    #pragma unroll
    for (int mi = 0; mi < MT; mi++)
        #pragma unroll
        for (int ni = 0; ni < NT; ni++)
            #pragma unroll
            for (int q = 0; q < 4; q++) acc[mi][ni][q] = 0.f;

    load_tile(0);
    for (int t = 0; t < T; t++){
        store_split();
        __syncthreads();
        if (t + 1 < T) load_tile(t + 1);
        #pragma unroll
        for (int kk = 0; kk < 2; kk++){
            int ko = kk * 8;
            unsigned ah[MT][4], al[MT][4];
            #pragma unroll
            for (int mi = 0; mi < MT; mi++){
                int mb = m0 + mi*16 + gid;
                ah[mi][0] = As[0][mb  ][ko+tig  ];
                ah[mi][1] = As[0][mb+8][ko+tig  ];
                ah[mi][2] = As[0][mb  ][ko+tig+4];
                ah[mi][3] = As[0][mb+8][ko+tig+4];
                al[mi][0] = As[1][mb  ][ko+tig  ];
                al[mi][1] = As[1][mb+8][ko+tig  ];
                al[mi][2] = As[1][mb  ][ko+tig+4];
                al[mi][3] = As[1][mb+8][ko+tig+4];
            }
            #pragma unroll
            for (int ni = 0; ni < NT; ni++){
                int nb = n0 + ni*8 + gid;
                unsigned bh0 = Bs[0][nb][ko+tig  ];
                unsigned bh1 = Bs[0][nb][ko+tig+4];
                unsigned bl0 = Bs[1][nb][ko+tig  ];
                unsigned bl1 = Bs[1][nb][ko+tig+4];
                #pragma unroll
                for (int mi = 0; mi < MT; mi++){
                    MMA_BF16(acc[mi][ni], ah[mi][0],ah[mi][1],ah[mi][2],ah[mi][3], bh0,bh1);
                    MMA_BF16(acc[mi][ni], ah[mi][0],ah[mi][1],ah[mi][2],ah[mi][3], bl0,bl1);
                    MMA_BF16(acc[mi][ni], al[mi][0],al[mi][1],al[mi][2],al[mi][3], bh0,bh1);
                }
            }
        }
        __syncthreads();
    }

    #pragma unroll
    for (int mi = 0; mi < MT; mi++){
        #pragma unroll
        for (int ni = 0; ni < NT; ni++){
            int cc = n0 + ni*8 + tig*2;
            #pragma unroll
            for (int h = 0; h < 2; h++){
                int rr = row0 + m0 + mi*16 + gid + h*8;
                if (rr < n){
                    float v0 = acc[mi][ni][h*2+0];
                    float v1 = acc[mi][ni][h*2+1];
                    if (bias){ v0 += __ldg(&bias[cc]); v1 += __ldg(&bias[cc+1]); }
                    if (D){ v0 += D[(size_t)rr*BN + cc]; v1 += D[(size_t)rr*BN + cc + 1]; }
                    if (RELU){ v0 = fmaxf(v0, 0.f); v1 = fmaxf(v1, 0.f); }
                    *(float2*)(out + (size_t)rr*BN + cc) = make_float2(v0, v1);
                }
            }
        }
    }
}

// ---------------- topk pooling ----------------
template<int C>
__global__ void score_kernel(const float* __restrict__ x, const float* __restrict__ w, int n)
{
    int gw = blockIdx.x*(blockDim.x>>5) + (threadIdx.x>>5);
    int lane = threadIdx.x & 31;
    if (gw >= n) return;
    float p, q;
    if constexpr (C == 128){
        float4 xv = ((const float4*)(x + (size_t)gw*128))[lane];
        float4 wv = ((const float4*)w)[lane];
        p = xv.x*wv.x + xv.y*wv.y + xv.z*wv.z + xv.w*wv.w;
        q = wv.x*wv.x + wv.y*wv.y + wv.z*wv.z + wv.w*wv.w;
    } else {
        float2 xv = ((const float2*)(x + (size_t)gw*64))[lane];
        float2 wv = ((const float2*)w)[lane];
        p = xv.x*wv.x + xv.y*wv.y;
        q = wv.x*wv.x + wv.y*wv.y;
    }
    #pragma unroll
    for (int off = 16; off; off >>= 1){
        p += __shfl_xor_sync(0xffffffffu, p, off);
        q += __shfl_xor_sync(0xffffffffu, q, off);
    }
    if (lane == 0){
        float s = tanhf(p / sqrtf(q));
        g_score[gw] = s;
        unsigned u = __float_as_uint(s);
        u = (u & 0x80000000u) ? ~u : (u | 0x80000000u);
        g_key[gw] = u;
    }
}

// ONE-KERNEL radix select + compact (single block, 1024 threads).
__global__ void __launch_bounds__(1024) topk_select_kernel(
    int* __restrict__ mapping, int* __restrict__ perm, int n, int k)
{
    __shared__ unsigned hist[256];
    __shared__ int ws[32];
    __shared__ int s_b, s_rem;

    unsigned prefix = 0;
    int remaining = k;
    for (int pass = 3; pass >= 0; pass--){
        for (int t = threadIdx.x; t < 256; t += 1024) hist[t] = 0;
        __syncthreads();
        int shf = (pass+1)*8;
        unsigned pref_hi = (pass == 3) ? 0u : (prefix >> shf);
        for (int base = 0; base < n; base += 1024){
            int i = base + threadIdx.x;
            if (i < n){
                unsigned key = g_key[i];
                bool ok = (pass == 3) || ((key >> shf) == pref_hi);
                if (ok) atomicAdd(&hist[(key >> (pass*8)) & 255], 1u);
            }
        }
        __syncthreads();
        if (threadIdx.x == 0){
            unsigned r = (unsigned)remaining;
            unsigned c = 0; int b = 255;
            for (; b > 0; b--){
                unsigned h = hist[b];
                if (c + h >= r) break;
                c += h;
            }
            s_b = b; s_rem = (int)(r - c);
        }
        __syncthreads();
        prefix |= ((unsigned)s_b) << (pass*8);
        remaining = s_rem;
        __syncthreads();
    }

    unsigned thr = prefix;
    int local = 0;
    for (int base = 0; base < n; base += 1024){
        int i = base + threadIdx.x;
        if (i < n) local += (g_key[i] > thr) ? 1 : 0;
    }
    int totG; block_scan_incl(local, totG, ws);
    int need_eq = k - totG;

    int run_eq = 0, run_sel = 0;
    for (int base = 0; base < n; base += 1024){
        int i = base + threadIdx.x;
        int gt = 0, eq = 0;
        if (i < n){
            unsigned kv = g_key[i];
            gt = (kv > thr); eq = (kv == thr);
        }
        int tot_eq; int incl_eq = block_scan_incl(eq, tot_eq, ws);
        int excl_eq = incl_eq - eq;
        int sel = gt | (eq & ((run_eq + excl_eq) < need_eq ? 1 : 0));
        int tot_sel; int incl_sel = block_scan_incl(sel, tot_sel, ws);
        if (i < n){
            if (sel){
                int idx = run_sel + incl_sel - 1;
                mapping[i] = idx;
                perm[idx] = i;
            } else mapping[i] = -1;
        }
        run_eq += tot_eq; run_sel += tot_sel;
    }
}

// fused compose of level0->level2 mapping and perm
__global__ void compose_kernel()
{
    int i = blockIdx.x*blockDim.x + threadIdx.x;
    if (i < N0){ int m = g_map1[i]; g_map02[i] = (m >= 0) ? g_map2[m] : -1; }
    if (i < K2) g_perm02[i] = g_perm1[g_perm2[i]];
}

template<int C>
__global__ void unpool_kernel(const float* __restrict__ xb, const float* __restrict__ xs,
                              const int* __restrict__ mapping, float* __restrict__ out, int n)
{
    int idx = blockIdx.x*blockDim.x + threadIdx.x;
    int total = n * (C/4);
    if (idx >= total) return;
    int i = idx / (C/4), t = idx % (C/4);
    int m = mapping[i];
    float4 v = ((const float4*)(xb + (size_t)i*C))[t];
    if (m >= 0){
        float4 w = ((const float4*)(xs + (size_t)m*C))[t];
        v.x += w.x; v.y += w.y; v.z += w.z; v.w += w.w;
    }
    ((float4*)(out + (size_t)i*C))[t] = v;
}

// ---------------- final linear + log_softmax (warp per node) ----------------
__global__ void final_kernel(const float* __restrict__ x, const float* __restrict__ lw,
                             const float* __restrict__ lb, float* __restrict__ out, int n)
{
    int gw = blockIdx.x*(blockDim.x>>5) + (threadIdx.x>>5);
    int lane = threadIdx.x & 31;
    if (gw >= n) return;
    float4 xv = ((const float4*)(x + (size_t)gw*128))[lane];
    float lg[10]; float myv = 0.f;
    #pragma unroll
    for (int c = 0; c < 10; c++){
        float4 wv = ((const float4*)(lw + c*128))[lane];
        float p = xv.x*wv.x + xv.y*wv.y + xv.z*wv.z + xv.w*wv.w;
        #pragma unroll
        for (int off = 16; off; off >>= 1) p += __shfl_xor_sync(0xffffffffu, p, off);
        p += __ldg(&lb[c]);
        lg[c] = p;
        if (lane == c) myv = p;
    }
    float m = lg[0];
    #pragma unroll
    for (int c = 1; c < 10; c++) m = fmaxf(m, lg[c]);
    float s = 0.f;
    #pragma unroll
    for (int c = 0; c < 10; c++) s += expf(lg[c] - m);
    float lse = m + logf(s);
    if (lane < 10) out[(size_t)gw*10 + lane] = myv - lse;
}

// ---------------- host driver ----------------
extern "C" void kernel_launch(void* const* d_in, const int* in_sizes, int n_in,
                              void* d_out, int out_size)
{
    (void)in_sizes; (void)n_in; (void)out_size;
    const float* x    = (const float*)d_in[0];
    const int*   ei   = (const int*)d_in[1];
    const int*   src0 = ei;
    const int*   dst0 = ei + E0;
    const float *w1r=(const float*)d_in[2], *w1o=(const float*)d_in[3], *b1=(const float*)d_in[4], *p1w=(const float*)d_in[5];
    const float *w2r=(const float*)d_in[6], *w2o=(const float*)d_in[7], *b2=(const float*)d_in[8], *p2w=(const float*)d_in[9];
    const float *w3r=(const float*)d_in[10],*w3o=(const float*)d_in[11],*b3=(const float*)d_in[12];
    const float *w4r=(const float*)d_in[13],*w4o=(const float*)d_in[14],*b4=(const float*)d_in[15];
    const float *w5r=(const float*)d_in[16],*w5o=(const float*)d_in[17],*b5=(const float*)d_in[18];
    const float *lw =(const float*)d_in[19],*lb =(const float*)d_in[20];
    float* out = (float*)d_out;

    float *x1,*agg,*tbuf,*x2,*x3,*u1,*x4,*u2,*x5,*wT,*score;
    int *rowptr,*fill,*part,*partx,*map1,*perm1,*map2,*perm2,*map02,*perm02;
    cudaGetSymbolAddress((void**)&x1, g_x1);
    cudaGetSymbolAddress((void**)&agg, g_agg);
    cudaGetSymbolAddress((void**)&tbuf, g_t);
    cudaGetSymbolAddress((void**)&x2, g_x2);
    cudaGetSymbolAddress((void**)&x3, g_x3);
    cudaGetSymbolAddress((void**)&u1, g_u1);
    cudaGetSymbolAddress((void**)&x4, g_x4);
    cudaGetSymbolAddress((void**)&u2, g_u2);
    cudaGetSymbolAddress((void**)&x5, g_x5);
    cudaGetSymbolAddress((void**)&wT, g_wT);
    cudaGetSymbolAddress((void**)&score, g_score);
    cudaGetSymbolAddress((void**)&rowptr, g_rowptr);
    cudaGetSymbolAddress((void**)&fill, g_fill);
    cudaGetSymbolAddress((void**)&part, g_part);
    cudaGetSymbolAddress((void**)&partx, g_partx);
    cudaGetSymbolAddress((void**)&map1, g_map1);
    cudaGetSymbolAddress((void**)&perm1, g_perm1);
    cudaGetSymbolAddress((void**)&map2, g_map2);
    cudaGetSymbolAddress((void**)&perm2, g_perm2);
    cudaGetSymbolAddress((void**)&map02, g_map02);
    cudaGetSymbolAddress((void**)&perm02, g_perm02);

    const int W = 16384;

    cudaStream_t s2;
    cudaEvent_t ev1, ev2;
    cudaStreamCreateWithFlags(&s2, cudaStreamNonBlocking);
    cudaEventCreateWithFlags(&ev1, cudaEventDisableTiming);
    cudaEventCreateWithFlags(&ev2, cudaEventDisableTiming);

    // fork s2 from main
    cudaEventRecord(ev1, 0);
    cudaStreamWaitEvent(s2, ev1, 0);

    // launch order: 1..3 small, 4 = tf32 GEMM (profiled)
    {
        dim3 g(64, 4);
        transpose_all_kernel<<<g,256>>>(w1r,w1o,w2r,w2o, wT);                    // 1 (main)
    }
    zero_int_kernel<<<(N0+255)/256,256,0,s2>>>(fill, N0);                        // 2 (s2)
    edge_count_kernel<<<(E0+255)/256,256,0,s2>>>(dst0);                          // 3 (s2)
    gemm_tc_kernel<128,128,false,false,false><<<(N0+127)/128,256>>>(             // 4 (main, profiled)
        x, nullptr, wT+1*W, nullptr, nullptr, nullptr, x1, N0, nullptr, nullptr);
    deg_reduce_kernel<<<NB_SCAN,1024,0,s2>>>(fill, part, N0);                    // 5 (s2)
    scan_kernel<<<1,1024,0,s2>>>(part, partx, NB_SCAN);                          // 6 (s2)
    deg_apply_kernel<<<NB_SCAN,1024,0,s2>>>(fill, partx, rowptr, N0);            // 7 (s2)
    edge_scatter_kernel<<<(E0+255)/256,256,0,s2>>>(src0, dst0);                  // 8 (s2)
    agg_kernel<128><<<(N0+7)/8,256,0,s2>>>(x, agg, nullptr, nullptr, N0);        // 9 (s2)
    cudaEventRecord(ev2, s2);
    cudaStreamWaitEvent(0, ev2, 0);

    // conv1 rel-half (in-place D add + bias + relu)
    gemm_tc_kernel<128,128,false,true,false><<<(N0+127)/128,256>>>(
        agg, nullptr, wT+0*W, nullptr, b1, x1, x1, N0, nullptr, nullptr);

    // pool1: score + single-kernel select
    score_kernel<128><<<(N0+7)/8,256>>>(x1, p1w, N0);
    topk_select_kernel<<<1,1024>>>(map1, perm1, N0, K1);

    // conv2: 128 -> 64 on level 1 (tf32; feeds pool2 scores)
    gemm_tc_kernel<64,128,false,false,true><<<(K1+127)/128,256>>>(
        x1, nullptr, wT+2*W, nullptr, nullptr, nullptr, tbuf, K1, perm1, score);
    agg_kernel<64><<<(K1+7)/8,256>>>(tbuf, agg, perm1, map1, K1);
    gemm_tc_kernel<64,128,false,true,true><<<(K1+127)/128,256>>>(
        x1, nullptr, wT+3*W, nullptr, b2, agg, x2, K1, perm1, score);

    // pool2
    score_kernel<64><<<(K1+7)/8,256>>>(x2, p2w, K1);
    topk_select_kernel<<<1,1024>>>(map2, perm2, K1, K2);

    // composed mappings level0 -> level2
    compose_kernel<<<(N0+255)/256,256>>>();

    // conv3: 64 -> 64 on level 2 (bf16-split)
    gemm_bf16_kernel<64,64,false,false,true><<<(K2+127)/128,256>>>(
        x2, nullptr, w3r, nullptr, nullptr, nullptr, tbuf, K2, perm2, score);
    agg_kernel<64><<<(K2+7)/8,256>>>(tbuf, agg, perm02, map02, K2);
    gemm_bf16_kernel<64,64,false,true,true><<<(K2+127)/128,256>>>(
        x2, nullptr, w3o, nullptr, b3, agg, x3, K2, perm2, score);

    // unpool1 + skip
    unpool_kernel<64><<<(K1*16+255)/256,256>>>(x2, x3, map2, u1, K1);

    // conv4: 64 -> 128 on level 1 (bf16-split)
    agg_kernel<64><<<(K1+7)/8,256>>>(u1, agg, perm1, map1, K1);
    gemm_bf16_kernel<128,64,true,true,false><<<(K1+127)/128,256>>>(
        agg, u1, w4r, w4o, b4, nullptr, x4, K1, nullptr, nullptr);

    // unpool2 + skip
    unpool_kernel<128><<<(N0*32+255)/256,256>>>(x1, x4, map1, u2, N0);

    // conv5: 128 -> 128 on level 0 (bf16-split)
    agg_kernel<128><<<(N0+7)/8,256>>>(u2, agg, nullptr, nullptr, N0);
    gemm_bf16_kernel<128,128,true,true,false><<<(N0+127)/128,256>>>(
        agg, u2, w5r, w5o, b5, nullptr, x5, N0, nullptr, nullptr);

    // final linear + log_softmax
    final_kernel<<<(N0+7)/8,256>>>(x5, lw, lb, out, N0);
}